// round 1
// baseline (speedup 1.0000x reference)
#include <cuda_runtime.h>
#include <math.h>

#define Bb 2
#define Cc 1024
#define Tt 2048
#define Hh 16
#define Dd 64
#define ATT_SCALE 0.125f  /* 1/sqrt(64) */

// ---------------- scratch (device globals: allocation-free) ----------------
__device__ float g_maskf[Bb * Tt];
__device__ float g_q[(size_t)Bb * Hh * Tt * Dd];
__device__ float g_k[(size_t)Bb * Hh * Tt * Dd];
__device__ float g_v[(size_t)Bb * Hh * Tt * Dd];
__device__ float g_ctx[(size_t)Bb * Cc * Tt];

// ---------------- mask normalization ----------------
// mask is logically bool[B,1,T]; storage dtype is ambiguous (u8 / i32 / f32).
// Detect deterministically: mask[0] is always True.
//   f32: word0 == 1.0f, all words in {0.0f, 1.0f}
//   i32: words in {0,1} (as float those are 0.0 / denormal -> f32 check fails)
//   u8 : off-aligned bytes nonzero -> both word checks fail
__global__ void mask_convert_kernel(const void* __restrict__ mraw) {
    __shared__ int fmt;
    if (threadIdx.x == 0) {
        const float* f = (const float*)mraw;
        const int* w = (const int*)mraw;
        bool isf = true, isi = true;
        for (int i = 0; i < Bb * Tt / 4; i++) {  // scan 4096 bytes (safe for u8 case)
            float v = f[i];
            if (!(v == 0.0f || v == 1.0f)) isf = false;
            int iv = w[i];
            if (!(iv == 0 || iv == 1)) isi = false;
        }
        fmt = isf ? 0 : (isi ? 1 : 2);
    }
    __syncthreads();
    int f = fmt;
    for (int i = threadIdx.x; i < Bb * Tt; i += blockDim.x) {
        float v;
        if (f == 0)      v = ((const float*)mraw)[i];
        else if (f == 1) v = (float)((const int*)mraw)[i];
        else             v = (float)((const unsigned char*)mraw)[i];
        g_maskf[i] = (v != 0.0f) ? 1.0f : 0.0f;
    }
}

// ---------------- projection GEMM ----------------
// out[o,t] = sum_c W[o,c] * X[b,c,t] + bias[o]
// MODE 0: store to head layout [B,H,T,D]                  (Q, K)
// MODE 1: head layout * mask[b,t]                         (V)
// MODE 2: [B,C,T] layout * mask[b,t]                      (final proj -> d_out)
template <int MODE>
__global__ void __launch_bounds__(256) proj_kernel(
    const float* __restrict__ W, const float* __restrict__ bias,
    const float* __restrict__ X, float* __restrict__ out)
{
    const int b = blockIdx.z;
    const float* x = X + (size_t)b * Cc * Tt;

    __shared__ float As[16][128];
    __shared__ float Bs[16][128];

    const int tid = threadIdx.x;
    const int tx = tid & 15;
    const int ty = tid >> 4;
    const int row0 = blockIdx.y * 128;
    const int col0 = blockIdx.x * 128;

    float acc[8][8];
#pragma unroll
    for (int i = 0; i < 8; i++)
#pragma unroll
        for (int j = 0; j < 8; j++) acc[i][j] = 0.0f;

    for (int k0 = 0; k0 < Cc; k0 += 16) {
#pragma unroll
        for (int i = 0; i < 2; i++) {
            int idx = tid + i * 256;      // 0..511 float4 slots of A tile
            int r = idx >> 2;             // 0..127 (o)
            int c4 = (idx & 3) << 2;      // 0,4,8,12 (c)
            float4 v = *(const float4*)(W + (size_t)(row0 + r) * Cc + k0 + c4);
            As[c4 + 0][r] = v.x;
            As[c4 + 1][r] = v.y;
            As[c4 + 2][r] = v.z;
            As[c4 + 3][r] = v.w;
        }
#pragma unroll
        for (int i = 0; i < 2; i++) {
            int idx = tid + i * 256;
            int r = idx >> 5;             // 0..15 (c)
            int c4 = (idx & 31) << 2;     // 0..124 (t)
            *(float4*)(&Bs[r][c4]) =
                *(const float4*)(x + (size_t)(k0 + r) * Tt + col0 + c4);
        }
        __syncthreads();
#pragma unroll
        for (int kk = 0; kk < 16; kk++) {
            float a[8], bb[8];
            *(float4*)&a[0] = *(const float4*)&As[kk][ty * 8];
            *(float4*)&a[4] = *(const float4*)&As[kk][ty * 8 + 4];
            *(float4*)&bb[0] = *(const float4*)&Bs[kk][tx * 8];
            *(float4*)&bb[4] = *(const float4*)&Bs[kk][tx * 8 + 4];
#pragma unroll
            for (int i = 0; i < 8; i++)
#pragma unroll
                for (int j = 0; j < 8; j++)
                    acc[i][j] = fmaf(a[i], bb[j], acc[i][j]);
        }
        __syncthreads();
    }

#pragma unroll
    for (int i = 0; i < 8; i++) {
        int o = row0 + ty * 8 + i;
        float bo = bias[o];
#pragma unroll
        for (int j = 0; j < 8; j++) {
            int t = col0 + tx * 8 + j;
            float val = acc[i][j] + bo;
            if (MODE == 0) {
                out[(((size_t)b * Hh + (o >> 6)) * Tt + t) * Dd + (o & 63)] = val;
            } else if (MODE == 1) {
                out[(((size_t)b * Hh + (o >> 6)) * Tt + t) * Dd + (o & 63)] =
                    val * g_maskf[b * Tt + t];
            } else {
                out[((size_t)b * Cc + o) * Tt + t] = val * g_maskf[b * Tt + t];
            }
        }
    }
}

// ---------------- fused attention (flash-style) ----------------
// One block: 64 queries of one (b,h). Iterates 64-key tiles.
// 256 threads = 16(ty: q groups) x 16(tx: key/d groups), 4x4 register tiles.
// Row stats (m, l) live in registers: row q = ty*4+i is owned by the 16
// threads sharing ty -> 16-lane shfl groups do the row reductions.
#define SM_STRIDE 68
__global__ void __launch_bounds__(256) attn_kernel(
    const float* __restrict__ Q, const float* __restrict__ K,
    const float* __restrict__ V, float* __restrict__ ctx)
{
    extern __shared__ float sm[];
    float* QT = sm;                        // [64][68]  Q^T (d-major), pre-scaled
    float* U  = sm + 64 * SM_STRIDE;       // [64][68]  K^T, then P^T
    float* Vs = sm + 2 * 64 * SM_STRIDE;   // [64][68]  V (key-major)
    float* ms = sm + 3 * 64 * SM_STRIDE;   // [64]      key mask

    const int tid = threadIdx.x;
    const int tx = tid & 15;
    const int ty = tid >> 4;
    const int bh = blockIdx.y;             // b*H + h
    const int b = bh >> 4;
    const int q0 = blockIdx.x * 64;

    const float* Qb = Q + (size_t)bh * Tt * Dd;
    const float* Kb = K + (size_t)bh * Tt * Dd;
    const float* Vb = V + (size_t)bh * Tt * Dd;

    // Load Q tile transposed & pre-scaled (once per block)
#pragma unroll
    for (int i = 0; i < 4; i++) {
        int idx = tid + i * 256;           // 0..1023
        int r = idx >> 4;                  // query row 0..63
        int d4 = (idx & 15) << 2;          // d 0..60
        float4 v = *(const float4*)(Qb + (size_t)(q0 + r) * Dd + d4);
        QT[(d4 + 0) * SM_STRIDE + r] = v.x * ATT_SCALE;
        QT[(d4 + 1) * SM_STRIDE + r] = v.y * ATT_SCALE;
        QT[(d4 + 2) * SM_STRIDE + r] = v.z * ATT_SCALE;
        QT[(d4 + 3) * SM_STRIDE + r] = v.w * ATT_SCALE;
    }

    float m[4], l[4], O[4][4];
#pragma unroll
    for (int i = 0; i < 4; i++) {
        m[i] = -3.0e38f;
        l[i] = 0.0f;
#pragma unroll
        for (int j = 0; j < 4; j++) O[i][j] = 0.0f;
    }

    for (int kt = 0; kt < Tt; kt += 64) {
        __syncthreads();  // previous-iter U/Vs reads complete
        // Load K tile transposed into U, V straight into Vs, mask into ms
#pragma unroll
        for (int i = 0; i < 4; i++) {
            int idx = tid + i * 256;
            int r = idx >> 4;
            int d4 = (idx & 15) << 2;
            float4 kv = *(const float4*)(Kb + (size_t)(kt + r) * Dd + d4);
            U[(d4 + 0) * SM_STRIDE + r] = kv.x;
            U[(d4 + 1) * SM_STRIDE + r] = kv.y;
            U[(d4 + 2) * SM_STRIDE + r] = kv.z;
            U[(d4 + 3) * SM_STRIDE + r] = kv.w;
            float4 vv = *(const float4*)(Vb + (size_t)(kt + r) * Dd + d4);
            *(float4*)&Vs[r * SM_STRIDE + d4] = vv;
        }
        if (tid < 64) ms[tid] = g_maskf[b * Tt + kt + tid];
        __syncthreads();

        // Phase A: S = (scaled Q) @ K^T ; s[i][j], q=ty*4+i, key=tx*4+j
        float s[4][4];
#pragma unroll
        for (int i = 0; i < 4; i++)
#pragma unroll
            for (int j = 0; j < 4; j++) s[i][j] = 0.0f;
#pragma unroll
        for (int d = 0; d < 64; d++) {
            float a[4], bb[4];
            *(float4*)a  = *(const float4*)&QT[d * SM_STRIDE + ty * 4];
            *(float4*)bb = *(const float4*)&U[d * SM_STRIDE + tx * 4];
#pragma unroll
            for (int i = 0; i < 4; i++)
#pragma unroll
                for (int j = 0; j < 4; j++)
                    s[i][j] = fmaf(a[i], bb[j], s[i][j]);
        }
        // Key mask
#pragma unroll
        for (int j = 0; j < 4; j++) {
            float mk = ms[tx * 4 + j];
#pragma unroll
            for (int i = 0; i < 4; i++)
                if (mk == 0.0f) s[i][j] = -1e30f;
        }
        // Online softmax (per-row, 16-lane shuffle reductions)
        float p[4][4];
        float alpha[4];
#pragma unroll
        for (int i = 0; i < 4; i++) {
            float mx = s[i][0];
#pragma unroll
            for (int j = 1; j < 4; j++) mx = fmaxf(mx, s[i][j]);
#pragma unroll
            for (int o = 1; o < 16; o <<= 1)
                mx = fmaxf(mx, __shfl_xor_sync(0xffffffffu, mx, o));
            float mnew = fmaxf(m[i], mx);
            float sum = 0.0f;
#pragma unroll
            for (int j = 0; j < 4; j++) {
                p[i][j] = __expf(s[i][j] - mnew);
                sum += p[i][j];
            }
#pragma unroll
            for (int o = 1; o < 16; o <<= 1)
                sum += __shfl_xor_sync(0xffffffffu, sum, o);
            alpha[i] = __expf(m[i] - mnew);
            l[i] = l[i] * alpha[i] + sum;
            m[i] = mnew;
        }
#pragma unroll
        for (int i = 0; i < 4; i++)
#pragma unroll
            for (int j = 0; j < 4; j++) O[i][j] *= alpha[i];

        __syncthreads();  // all K^T reads done; U can be repurposed
        // Write P^T into U: U[key][q]
#pragma unroll
        for (int j = 0; j < 4; j++)
#pragma unroll
            for (int i = 0; i < 4; i++)
                U[(tx * 4 + j) * SM_STRIDE + ty * 4 + i] = p[i][j];
        __syncthreads();

        // Phase B: O += P @ V  (q=ty*4+i rows, d=tx*4+j cols)
#pragma unroll
        for (int k = 0; k < 64; k++) {
            float a[4], bb[4];
            *(float4*)a  = *(const float4*)&U[k * SM_STRIDE + ty * 4];
            *(float4*)bb = *(const float4*)&Vs[k * SM_STRIDE + tx * 4];
#pragma unroll
            for (int i = 0; i < 4; i++)
#pragma unroll
                for (int j = 0; j < 4; j++)
                    O[i][j] = fmaf(a[i], bb[j], O[i][j]);
        }
    }

    // Epilogue: ctx[b, h*64+d, q] = O / l
    const int h = bh & 15;
#pragma unroll
    for (int i = 0; i < 4; i++) {
        float inv = 1.0f / l[i];
        int qg = q0 + ty * 4 + i;
#pragma unroll
        for (int j = 0; j < 4; j++) {
            int d = tx * 4 + j;
            ctx[((size_t)b * Cc + h * 64 + d) * Tt + qg] = O[i][j] * inv;
        }
    }
}

// ---------------- mask echo (second tuple output) ----------------
__global__ void mask_out_kernel(float* __restrict__ out) {
    int i = blockIdx.x * blockDim.x + threadIdx.x;
    if (i < Bb * Tt) out[i] = g_maskf[i];
}

// ---------------- launch ----------------
extern "C" void kernel_launch(void* const* d_in, const int* in_sizes, int n_in,
                              void* d_out, int out_size)
{
    const float* x  = (const float*)d_in[0];
    const void*  mk = d_in[1];
    const float* Wq = (const float*)d_in[2];
    const float* bq = (const float*)d_in[3];
    const float* Wk = (const float*)d_in[4];
    const float* bk = (const float*)d_in[5];
    const float* Wv = (const float*)d_in[6];
    const float* bv = (const float*)d_in[7];
    const float* Wp = (const float*)d_in[8];
    const float* bp = (const float*)d_in[9];
    float* out = (float*)d_out;

    float *qp, *kp, *vp, *cp;
    cudaGetSymbolAddress((void**)&qp, g_q);
    cudaGetSymbolAddress((void**)&kp, g_k);
    cudaGetSymbolAddress((void**)&vp, g_v);
    cudaGetSymbolAddress((void**)&cp, g_ctx);

    const int attn_smem = (3 * 64 * SM_STRIDE + 64) * (int)sizeof(float);
    cudaFuncSetAttribute(attn_kernel,
                         cudaFuncAttributeMaxDynamicSharedMemorySize, attn_smem);

    mask_convert_kernel<<<1, 256>>>(mk);

    dim3 pg(Tt / 128, Cc / 128, Bb);  // (16, 8, 2)
    proj_kernel<0><<<pg, 256>>>(Wq, bq, x, qp);
    proj_kernel<0><<<pg, 256>>>(Wk, bk, x, kp);
    proj_kernel<1><<<pg, 256>>>(Wv, bv, x, vp);

    attn_kernel<<<dim3(Tt / 64, Bb * Hh), 256, attn_smem>>>(qp, kp, vp, cp);

    proj_kernel<2><<<pg, 256>>>(Wp, bp, cp, out);

    if (out_size >= Bb * Cc * Tt + Bb * Tt) {
        mask_out_kernel<<<(Bb * Tt + 255) / 256, 256>>>(out + (size_t)Bb * Cc * Tt);
    }
}

// round 3
// speedup vs baseline: 1.4741x; 1.4741x over previous
#include <cuda_runtime.h>
#include <cuda_bf16.h>
#include <cstdint>
#include <math.h>

#define Bb 2
#define Cc 1024
#define Tt 2048
#define Hh 16
#define Dd 64
#define ATT_SCALE 0.125f  /* 1/sqrt(64) */

typedef __nv_bfloat16 bf16;

// ---------------- scratch (device globals: allocation-free) ----------------
__device__ float g_maskf[Bb * Tt];
__device__ float g_q[(size_t)Bb * Hh * Tt * Dd];
__device__ float g_k[(size_t)Bb * Hh * Tt * Dd];
__device__ float g_v[(size_t)Bb * Hh * Tt * Dd];
__device__ float g_ctx[(size_t)Bb * Cc * Tt];
// bf16 split operands
__device__ bf16 g_Wqh[Cc * Cc], g_Wql[Cc * Cc];
__device__ bf16 g_Wkh[Cc * Cc], g_Wkl[Cc * Cc];
__device__ bf16 g_Wvh[Cc * Cc], g_Wvl[Cc * Cc];
__device__ bf16 g_Wph[Cc * Cc], g_Wpl[Cc * Cc];
__device__ bf16 g_Xth[(size_t)Bb * Tt * Cc], g_Xtl[(size_t)Bb * Tt * Cc];
__device__ bf16 g_Cth[(size_t)Bb * Tt * Cc], g_Ctl[(size_t)Bb * Tt * Cc];

// ======================= helpers =======================
__device__ __forceinline__ uint32_t smem_to_u32(const void* p) {
    uint32_t a;
    asm("{ .reg .u64 t; cvta.to.shared.u64 t, %1; cvt.u32.u64 %0, t; }"
        : "=r"(a) : "l"(p));
    return a;
}
#define CP_ASYNC16(saddr, gptr) \
    asm volatile("cp.async.cg.shared.global [%0], [%1], 16;" \
        :: "r"(saddr), "l"(gptr) : "memory")
#define CP_COMMIT() asm volatile("cp.async.commit_group;" ::: "memory")
#define CP_WAIT(N)  asm volatile("cp.async.wait_group %0;" :: "n"(N) : "memory")
#define LDMATRIX_X4(r0, r1, r2, r3, addr) \
    asm volatile("ldmatrix.sync.aligned.m8n8.x4.shared.b16 {%0,%1,%2,%3}, [%4];" \
        : "=r"(r0), "=r"(r1), "=r"(r2), "=r"(r3) : "r"(addr))
#define MMA_BF16(c, a, b) \
    asm volatile("mma.sync.aligned.m16n8k16.row.col.f32.bf16.bf16.f32 " \
        "{%0,%1,%2,%3}, {%4,%5,%6,%7}, {%8,%9}, {%0,%1,%2,%3};" \
        : "+f"((c)[0]), "+f"((c)[1]), "+f"((c)[2]), "+f"((c)[3]) \
        : "r"((a)[0]), "r"((a)[1]), "r"((a)[2]), "r"((a)[3]), \
          "r"((b)[0]), "r"((b)[1]))

// ---------------- mask normalization ----------------
__global__ void mask_convert_kernel(const void* __restrict__ mraw) {
    const int tid = threadIdx.x;
    bool isf = true, isi = true;
    const float* f = (const float*)mraw;
    const int* w = (const int*)mraw;
    for (int i = tid; i < Bb * Tt / 4; i += 256) {
        float v = f[i];
        if (!(v == 0.0f || v == 1.0f)) isf = false;
        int iv = w[i];
        if (!(iv == 0 || iv == 1)) isi = false;
    }
    int allf = __syncthreads_and(isf ? 1 : 0);
    int alli = __syncthreads_and(isi ? 1 : 0);
    int fmt = allf ? 0 : (alli ? 1 : 2);
    for (int i = tid; i < Bb * Tt; i += 256) {
        float v;
        if (fmt == 0)      v = ((const float*)mraw)[i];
        else if (fmt == 1) v = (float)((const int*)mraw)[i];
        else               v = (float)((const unsigned char*)mraw)[i];
        g_maskf[i] = (v != 0.0f) ? 1.0f : 0.0f;
    }
}

// ---------------- conversions ----------------
__global__ void convw_kernel(const float* __restrict__ s,
                             bf16* __restrict__ h, bf16* __restrict__ l) {
    int i = blockIdx.x * 256 + threadIdx.x;  // grid sized exactly Cc*Cc/256
    float v = s[i];
    bf16 hi = __float2bfloat16(v);
    h[i] = hi;
    l[i] = __float2bfloat16(v - __bfloat162float(hi));
}

// src [b][C][T] f32 -> dst [b][T][C] bf16 hi/lo (transpose + split)
__global__ void convT_kernel(const float* __restrict__ src,
                             bf16* __restrict__ dh, bf16* __restrict__ dl) {
    __shared__ float tile[32][33];
    const int b = blockIdx.z;
    const int t0 = blockIdx.x * 32;
    const int c0 = blockIdx.y * 32;
    const float* s = src + (size_t)b * Cc * Tt;
    bf16* oh = dh + (size_t)b * Tt * Cc;
    bf16* ol = dl + (size_t)b * Tt * Cc;
    const int tx = threadIdx.x;  // 32
    const int ty = threadIdx.y;  // 8
#pragma unroll
    for (int i = ty; i < 32; i += 8)
        tile[i][tx] = s[(size_t)(c0 + i) * Tt + t0 + tx];
    __syncthreads();
#pragma unroll
    for (int i = ty; i < 32; i += 8) {
        float v = tile[tx][i];  // src[c0+tx][t0+i]
        bf16 hi = __float2bfloat16(v);
        size_t idx = (size_t)(t0 + i) * Cc + c0 + tx;
        oh[idx] = hi;
        ol[idx] = __float2bfloat16(v - __bfloat162float(hi));
    }
}

// ---------------- bf16 split-2 tensor-core projection GEMM ----------------
// out[o,t] = sum_c W[o,c]*X[c,t] (+bias, epilogue per MODE)
// A = W [o][c] bf16 hi/lo; B = X^T [t][c] bf16 hi/lo (both k-pairs contiguous).
// MODE 0: head layout [B,H,T,D]; MODE 1: head layout * mask; MODE 2: [B,C,T]*mask
#define BM 128
#define BN 128
#define BK 32
#define ROWB 80                   /* padded bytes per 32-elem bf16 row */
#define TILE_B (128 * ROWB)       /* 10240 */
#define STAGE_B (4 * TILE_B)      /* 40960 */
#define PJ_SMEM (2 * STAGE_B)     /* 81920 */

template <int MODE>
__global__ void __launch_bounds__(256) proj_mma_kernel(
    const bf16* __restrict__ Ah, const bf16* __restrict__ Al,
    const float* __restrict__ bias,
    const bf16* __restrict__ Bth, const bf16* __restrict__ Btl,
    float* __restrict__ out)
{
    extern __shared__ char smem[];
    const uint32_t sb = smem_to_u32(smem);
    const int tid = threadIdx.x;
    const int wid = tid >> 5;
    const int lane = tid & 31;
    const int b = blockIdx.z;
    const int row0 = blockIdx.y * BM;  // o
    const int col0 = blockIdx.x * BN;  // t
    const bf16* Bh = Bth + (size_t)b * Tt * Cc;
    const bf16* Bl = Btl + (size_t)b * Tt * Cc;

    const int wm = (wid >> 2) * 64;
    const int wn = (wid & 3) * 32;

    // cp.async mapping: chunk = row*4+ch over 128x4; thread does chunks tid, tid+256
    const int lr = tid >> 2;       // row 0..63 (and +64)
    const int lch = tid & 3;       // 16B chunk 0..3

    // ldmatrix lane address components
    const int rowA = (((lane >> 3) & 1) << 3) + (lane & 7);
    const int colA = (lane >> 4) << 3;
    const int rowB = ((lane >> 4) << 3) + (lane & 7);
    const int colB = ((lane >> 3) & 1) << 3;

    float acc[4][4][4];
#pragma unroll
    for (int mi = 0; mi < 4; mi++)
#pragma unroll
        for (int ni = 0; ni < 4; ni++)
#pragma unroll
            for (int e = 0; e < 4; e++) acc[mi][ni][e] = 0.0f;

    const int NK = Cc / BK;  // 32

    // ---- prefetch stage 0 ----
    {
        const int k0 = 0;
        uint32_t s0 = sb;
#pragma unroll
        for (int j = 0; j < 2; j++) {
            int r = lr + j * 64;
            uint32_t so = (uint32_t)(r * ROWB + lch * 16);
            int ge = k0 + lch * 8;
            CP_ASYNC16(s0 + so,              Ah + (size_t)(row0 + r) * Cc + ge);
            CP_ASYNC16(s0 + TILE_B + so,     Al + (size_t)(row0 + r) * Cc + ge);
            CP_ASYNC16(s0 + 2 * TILE_B + so, Bh + (size_t)(col0 + r) * Cc + ge);
            CP_ASYNC16(s0 + 3 * TILE_B + so, Bl + (size_t)(col0 + r) * Cc + ge);
        }
        CP_COMMIT();
    }

#pragma unroll 1
    for (int ks = 0; ks < NK; ks++) {
        const int p = ks & 1;
        if (ks + 1 < NK) {
            const int k0 = (ks + 1) * BK;
            uint32_t s0 = sb + (p ^ 1) * STAGE_B;
#pragma unroll
            for (int j = 0; j < 2; j++) {
                int r = lr + j * 64;
                uint32_t so = (uint32_t)(r * ROWB + lch * 16);
                int ge = k0 + lch * 8;
                CP_ASYNC16(s0 + so,              Ah + (size_t)(row0 + r) * Cc + ge);
                CP_ASYNC16(s0 + TILE_B + so,     Al + (size_t)(row0 + r) * Cc + ge);
                CP_ASYNC16(s0 + 2 * TILE_B + so, Bh + (size_t)(col0 + r) * Cc + ge);
                CP_ASYNC16(s0 + 3 * TILE_B + so, Bl + (size_t)(col0 + r) * Cc + ge);
            }
            CP_COMMIT();
            CP_WAIT(1);
        } else {
            CP_WAIT(0);
        }
        __syncthreads();

        const uint32_t sAh = sb + p * STAGE_B;
        const uint32_t sAl = sAh + TILE_B;
        const uint32_t sBh = sAh + 2 * TILE_B;
        const uint32_t sBl = sAh + 3 * TILE_B;

#pragma unroll
        for (int kk = 0; kk < 32; kk += 16) {
            uint32_t a_h[4][4], a_l[4][4];
#pragma unroll
            for (int mi = 0; mi < 4; mi++) {
                uint32_t off = (uint32_t)((wm + mi * 16 + rowA) * ROWB +
                                          (kk + colA) * 2);
                LDMATRIX_X4(a_h[mi][0], a_h[mi][1], a_h[mi][2], a_h[mi][3], sAh + off);
                LDMATRIX_X4(a_l[mi][0], a_l[mi][1], a_l[mi][2], a_l[mi][3], sAl + off);
            }
            uint32_t b_h[4][2], b_l[4][2];
#pragma unroll
            for (int pr = 0; pr < 2; pr++) {
                uint32_t off = (uint32_t)((wn + pr * 16 + rowB) * ROWB +
                                          (kk + colB) * 2);
                LDMATRIX_X4(b_h[2 * pr][0], b_h[2 * pr][1],
                            b_h[2 * pr + 1][0], b_h[2 * pr + 1][1], sBh + off);
                LDMATRIX_X4(b_l[2 * pr][0], b_l[2 * pr][1],
                            b_l[2 * pr + 1][0], b_l[2 * pr + 1][1], sBl + off);
            }
#pragma unroll
            for (int mi = 0; mi < 4; mi++)
#pragma unroll
                for (int ni = 0; ni < 4; ni++) {
                    MMA_BF16(acc[mi][ni], a_h[mi], b_h[ni]);
                    MMA_BF16(acc[mi][ni], a_h[mi], b_l[ni]);
                    MMA_BF16(acc[mi][ni], a_l[mi], b_h[ni]);
                }
        }
        __syncthreads();
    }

    // ---- epilogue ----
    const int g = lane >> 2;
    const int tig = lane & 3;
#pragma unroll
    for (int mi = 0; mi < 4; mi++) {
#pragma unroll
        for (int part = 0; part < 2; part++) {
            const int o = row0 + wm + mi * 16 + g + part * 8;
            const float bo = bias[o];
#pragma unroll
            for (int ni = 0; ni < 4; ni++) {
#pragma unroll
                for (int e = 0; e < 2; e++) {
                    const int t = col0 + wn + ni * 8 + tig * 2 + e;
                    float v = acc[mi][ni][part * 2 + e] + bo;
                    if (MODE == 0) {
                        out[(((size_t)b * Hh + (o >> 6)) * Tt + t) * Dd + (o & 63)] = v;
                    } else if (MODE == 1) {
                        out[(((size_t)b * Hh + (o >> 6)) * Tt + t) * Dd + (o & 63)] =
                            v * g_maskf[b * Tt + t];
                    } else {
                        out[((size_t)b * Cc + o) * Tt + t] = v * g_maskf[b * Tt + t];
                    }
                }
            }
        }
    }
}

// ---------------- fused attention (flash-style, fp32 — unchanged) ----------------
#define SM_STRIDE 68
__global__ void __launch_bounds__(256) attn_kernel(
    const float* __restrict__ Q, const float* __restrict__ K,
    const float* __restrict__ V, float* __restrict__ ctx)
{
    extern __shared__ float sm[];
    float* QT = sm;
    float* U  = sm + 64 * SM_STRIDE;
    float* Vs = sm + 2 * 64 * SM_STRIDE;
    float* ms = sm + 3 * 64 * SM_STRIDE;

    const int tid = threadIdx.x;
    const int tx = tid & 15;
    const int ty = tid >> 4;
    const int bh = blockIdx.y;
    const int b = bh >> 4;
    const int q0 = blockIdx.x * 64;

    const float* Qb = Q + (size_t)bh * Tt * Dd;
    const float* Kb = K + (size_t)bh * Tt * Dd;
    const float* Vb = V + (size_t)bh * Tt * Dd;

#pragma unroll
    for (int i = 0; i < 4; i++) {
        int idx = tid + i * 256;
        int r = idx >> 4;
        int d4 = (idx & 15) << 2;
        float4 v = *(const float4*)(Qb + (size_t)(q0 + r) * Dd + d4);
        QT[(d4 + 0) * SM_STRIDE + r] = v.x * ATT_SCALE;
        QT[(d4 + 1) * SM_STRIDE + r] = v.y * ATT_SCALE;
        QT[(d4 + 2) * SM_STRIDE + r] = v.z * ATT_SCALE;
        QT[(d4 + 3) * SM_STRIDE + r] = v.w * ATT_SCALE;
    }

    float m[4], l[4], O[4][4];
#pragma unroll
    for (int i = 0; i < 4; i++) {
        m[i] = -3.0e38f;
        l[i] = 0.0f;
#pragma unroll
        for (int j = 0; j < 4; j++) O[i][j] = 0.0f;
    }

    for (int kt = 0; kt < Tt; kt += 64) {
        __syncthreads();
#pragma unroll
        for (int i = 0; i < 4; i++) {
            int idx = tid + i * 256;
            int r = idx >> 4;
            int d4 = (idx & 15) << 2;
            float4 kv = *(const float4*)(Kb + (size_t)(kt + r) * Dd + d4);
            U[(d4 + 0) * SM_STRIDE + r] = kv.x;
            U[(d4 + 1) * SM_STRIDE + r] = kv.y;
            U[(d4 + 2) * SM_STRIDE + r] = kv.z;
            U[(d4 + 3) * SM_STRIDE + r] = kv.w;
            float4 vv = *(const float4*)(Vb + (size_t)(kt + r) * Dd + d4);
            *(float4*)&Vs[r * SM_STRIDE + d4] = vv;
        }
        if (tid < 64) ms[tid] = g_maskf[b * Tt + kt + tid];
        __syncthreads();

        float s[4][4];
#pragma unroll
        for (int i = 0; i < 4; i++)
#pragma unroll
            for (int j = 0; j < 4; j++) s[i][j] = 0.0f;
#pragma unroll
        for (int d = 0; d < 64; d++) {
            float a[4], bb[4];
            *(float4*)a  = *(const float4*)&QT[d * SM_STRIDE + ty * 4];
            *(float4*)bb = *(const float4*)&U[d * SM_STRIDE + tx * 4];
#pragma unroll
            for (int i = 0; i < 4; i++)
#pragma unroll
                for (int j = 0; j < 4; j++)
                    s[i][j] = fmaf(a[i], bb[j], s[i][j]);
        }
#pragma unroll
        for (int j = 0; j < 4; j++) {
            float mk = ms[tx * 4 + j];
#pragma unroll
            for (int i = 0; i < 4; i++)
                if (mk == 0.0f) s[i][j] = -1e30f;
        }
        float p[4][4];
        float alpha[4];
#pragma unroll
        for (int i = 0; i < 4; i++) {
            float mx = s[i][0];
#pragma unroll
            for (int j = 1; j < 4; j++) mx = fmaxf(mx, s[i][j]);
#pragma unroll
            for (int o = 1; o < 16; o <<= 1)
                mx = fmaxf(mx, __shfl_xor_sync(0xffffffffu, mx, o));
            float mnew = fmaxf(m[i], mx);
            float sum = 0.0f;
#pragma unroll
            for (int j = 0; j < 4; j++) {
                p[i][j] = __expf(s[i][j] - mnew);
                sum += p[i][j];
            }
#pragma unroll
            for (int o = 1; o < 16; o <<= 1)
                sum += __shfl_xor_sync(0xffffffffu, sum, o);
            alpha[i] = __expf(m[i] - mnew);
            l[i] = l[i] * alpha[i] + sum;
            m[i] = mnew;
        }
#pragma unroll
        for (int i = 0; i < 4; i++)
#pragma unroll
            for (int j = 0; j < 4; j++) O[i][j] *= alpha[i];

        __syncthreads();
#pragma unroll
        for (int j = 0; j < 4; j++)
#pragma unroll
            for (int i = 0; i < 4; i++)
                U[(tx * 4 + j) * SM_STRIDE + ty * 4 + i] = p[i][j];
        __syncthreads();

#pragma unroll
        for (int k = 0; k < 64; k++) {
            float a[4], bb[4];
            *(float4*)a  = *(const float4*)&U[k * SM_STRIDE + ty * 4];
            *(float4*)bb = *(const float4*)&Vs[k * SM_STRIDE + tx * 4];
#pragma unroll
            for (int i = 0; i < 4; i++)
#pragma unroll
                for (int j = 0; j < 4; j++)
                    O[i][j] = fmaf(a[i], bb[j], O[i][j]);
        }
    }

    const int h = bh & 15;
#pragma unroll
    for (int i = 0; i < 4; i++) {
        float inv = 1.0f / l[i];
        int qg = q0 + ty * 4 + i;
#pragma unroll
        for (int j = 0; j < 4; j++) {
            int d = tx * 4 + j;
            ctx[((size_t)b * Cc + h * 64 + d) * Tt + qg] = O[i][j] * inv;
        }
    }
}

// ---------------- mask echo (second tuple output) ----------------
__global__ void mask_out_kernel(float* __restrict__ out) {
    int i = blockIdx.x * blockDim.x + threadIdx.x;
    if (i < Bb * Tt) out[i] = g_maskf[i];
}

// ---------------- launch ----------------
extern "C" void kernel_launch(void* const* d_in, const int* in_sizes, int n_in,
                              void* d_out, int out_size)
{
    const float* x  = (const float*)d_in[0];
    const void*  mk = d_in[1];
    const float* Wq = (const float*)d_in[2];
    const float* bq = (const float*)d_in[3];
    const float* Wk = (const float*)d_in[4];
    const float* bk = (const float*)d_in[5];
    const float* Wv = (const float*)d_in[6];
    const float* bv = (const float*)d_in[7];
    const float* Wp = (const float*)d_in[8];
    const float* bp = (const float*)d_in[9];
    float* out = (float*)d_out;

    float *qp, *kp, *vp, *cp;
    cudaGetSymbolAddress((void**)&qp, g_q);
    cudaGetSymbolAddress((void**)&kp, g_k);
    cudaGetSymbolAddress((void**)&vp, g_v);
    cudaGetSymbolAddress((void**)&cp, g_ctx);
    bf16 *wqh, *wql, *wkh, *wkl, *wvh, *wvl, *wph, *wpl, *xth, *xtl, *cth, *ctl;
    cudaGetSymbolAddress((void**)&wqh, g_Wqh); cudaGetSymbolAddress((void**)&wql, g_Wql);
    cudaGetSymbolAddress((void**)&wkh, g_Wkh); cudaGetSymbolAddress((void**)&wkl, g_Wkl);
    cudaGetSymbolAddress((void**)&wvh, g_Wvh); cudaGetSymbolAddress((void**)&wvl, g_Wvl);
    cudaGetSymbolAddress((void**)&wph, g_Wph); cudaGetSymbolAddress((void**)&wpl, g_Wpl);
    cudaGetSymbolAddress((void**)&xth, g_Xth); cudaGetSymbolAddress((void**)&xtl, g_Xtl);
    cudaGetSymbolAddress((void**)&cth, g_Cth); cudaGetSymbolAddress((void**)&ctl, g_Ctl);

    cudaFuncSetAttribute(proj_mma_kernel<0>,
                         cudaFuncAttributeMaxDynamicSharedMemorySize, PJ_SMEM);
    cudaFuncSetAttribute(proj_mma_kernel<1>,
                         cudaFuncAttributeMaxDynamicSharedMemorySize, PJ_SMEM);
    cudaFuncSetAttribute(proj_mma_kernel<2>,
                         cudaFuncAttributeMaxDynamicSharedMemorySize, PJ_SMEM);
    const int attn_smem = (3 * 64 * SM_STRIDE + 64) * (int)sizeof(float);
    cudaFuncSetAttribute(attn_kernel,
                         cudaFuncAttributeMaxDynamicSharedMemorySize, attn_smem);

    mask_convert_kernel<<<1, 256>>>(mk);

    const int wblocks = Cc * Cc / 256;
    convw_kernel<<<wblocks, 256>>>(Wq, wqh, wql);
    convw_kernel<<<wblocks, 256>>>(Wk, wkh, wkl);
    convw_kernel<<<wblocks, 256>>>(Wv, wvh, wvl);
    convw_kernel<<<wblocks, 256>>>(Wp, wph, wpl);
    convT_kernel<<<dim3(Tt / 32, Cc / 32, Bb), dim3(32, 8)>>>(x, xth, xtl);

    dim3 pg(Tt / BN, Cc / BM, Bb);  // (16, 8, 2)
    proj_mma_kernel<0><<<pg, 256, PJ_SMEM>>>(wqh, wql, bq, xth, xtl, qp);
    proj_mma_kernel<0><<<pg, 256, PJ_SMEM>>>(wkh, wkl, bk, xth, xtl, kp);
    proj_mma_kernel<1><<<pg, 256, PJ_SMEM>>>(wvh, wvl, bv, xth, xtl, vp);

    attn_kernel<<<dim3(Tt / 64, Bb * Hh), 256, attn_smem>>>(qp, kp, vp, cp);

    convT_kernel<<<dim3(Tt / 32, Cc / 32, Bb), dim3(32, 8)>>>(cp, cth, ctl);
    proj_mma_kernel<2><<<pg, 256, PJ_SMEM>>>(wph, wpl, bp, cth, ctl, out);

    if (out_size >= Bb * Cc * Tt + Bb * Tt) {
        mask_out_kernel<<<(Bb * Tt + 255) / 256, 256>>>(out + (size_t)Bb * Cc * Tt);
    }
}

// round 4
// speedup vs baseline: 2.5529x; 1.7318x over previous
#include <cuda_runtime.h>
#include <cuda_bf16.h>
#include <cstdint>
#include <math.h>

#define Bb 2
#define Cc 1024
#define Tt 2048
#define Hh 16
#define Dd 64
#define ATT_SCALE 0.125f  /* 1/sqrt(64) */

typedef __nv_bfloat16 bf16;

// ---------------- scratch (device globals: allocation-free) ----------------
__device__ float g_maskf[Bb * Tt];
// bf16 split weights
__device__ bf16 g_Wqh[Cc * Cc], g_Wql[Cc * Cc];
__device__ bf16 g_Wkh[Cc * Cc], g_Wkl[Cc * Cc];
__device__ bf16 g_Wvh[Cc * Cc], g_Wvl[Cc * Cc];
__device__ bf16 g_Wph[Cc * Cc], g_Wpl[Cc * Cc];
// X^T split
__device__ bf16 g_Xth[(size_t)Bb * Tt * Cc], g_Xtl[(size_t)Bb * Tt * Cc];
// Q/K/V head layout [B,H,T,D] split
__device__ bf16 g_Qh[(size_t)Bb * Hh * Tt * Dd], g_Ql[(size_t)Bb * Hh * Tt * Dd];
__device__ bf16 g_Kh[(size_t)Bb * Hh * Tt * Dd], g_Kl[(size_t)Bb * Hh * Tt * Dd];
__device__ bf16 g_Vh[(size_t)Bb * Hh * Tt * Dd], g_Vl[(size_t)Bb * Hh * Tt * Dd];
// ctx^T split [B,T,C] (B-operand layout for output projection)
__device__ bf16 g_Cth[(size_t)Bb * Tt * Cc], g_Ctl[(size_t)Bb * Tt * Cc];

// ======================= helpers =======================
__device__ __forceinline__ uint32_t smem_to_u32(const void* p) {
    uint32_t a;
    asm("{ .reg .u64 t; cvta.to.shared.u64 t, %1; cvt.u32.u64 %0, t; }"
        : "=r"(a) : "l"(p));
    return a;
}
#define CP_ASYNC16(saddr, gptr) \
    asm volatile("cp.async.cg.shared.global [%0], [%1], 16;" \
        :: "r"(saddr), "l"(gptr) : "memory")
#define CP_COMMIT() asm volatile("cp.async.commit_group;" ::: "memory")
#define CP_WAIT(N)  asm volatile("cp.async.wait_group %0;" :: "n"(N) : "memory")
#define LDMATRIX_X4(r0, r1, r2, r3, addr) \
    asm volatile("ldmatrix.sync.aligned.m8n8.x4.shared.b16 {%0,%1,%2,%3}, [%4];" \
        : "=r"(r0), "=r"(r1), "=r"(r2), "=r"(r3) : "r"(addr))
#define LDMATRIX_X4T(r0, r1, r2, r3, addr) \
    asm volatile("ldmatrix.sync.aligned.m8n8.x4.trans.shared.b16 {%0,%1,%2,%3}, [%4];" \
        : "=r"(r0), "=r"(r1), "=r"(r2), "=r"(r3) : "r"(addr))
#define MMA_BF16(c, a, b) \
    asm volatile("mma.sync.aligned.m16n8k16.row.col.f32.bf16.bf16.f32 " \
        "{%0,%1,%2,%3}, {%4,%5,%6,%7}, {%8,%9}, {%0,%1,%2,%3};" \
        : "+f"((c)[0]), "+f"((c)[1]), "+f"((c)[2]), "+f"((c)[3]) \
        : "r"((a)[0]), "r"((a)[1]), "r"((a)[2]), "r"((a)[3]), \
          "r"((b)[0]), "r"((b)[1]))

__device__ __forceinline__ uint32_t pack_bf2(float x, float y) {
    __nv_bfloat162 t = __floats2bfloat162_rn(x, y);
    return *(uint32_t*)&t;
}

// ---------------- mask normalization ----------------
__global__ void mask_convert_kernel(const void* __restrict__ mraw) {
    const int tid = threadIdx.x;
    bool isf = true, isi = true;
    const float* f = (const float*)mraw;
    const int* w = (const int*)mraw;
    for (int i = tid; i < Bb * Tt / 4; i += 256) {
        float v = f[i];
        if (!(v == 0.0f || v == 1.0f)) isf = false;
        int iv = w[i];
        if (!(iv == 0 || iv == 1)) isi = false;
    }
    int allf = __syncthreads_and(isf ? 1 : 0);
    int alli = __syncthreads_and(isi ? 1 : 0);
    int fmt = allf ? 0 : (alli ? 1 : 2);
    for (int i = tid; i < Bb * Tt; i += 256) {
        float v;
        if (fmt == 0)      v = ((const float*)mraw)[i];
        else if (fmt == 1) v = (float)((const int*)mraw)[i];
        else               v = (float)((const unsigned char*)mraw)[i];
        g_maskf[i] = (v != 0.0f) ? 1.0f : 0.0f;
    }
}

// ---------------- conversions ----------------
__global__ void convw_kernel(const float* __restrict__ s,
                             bf16* __restrict__ h, bf16* __restrict__ l) {
    int i = blockIdx.x * 256 + threadIdx.x;
    float v = s[i];
    bf16 hi = __float2bfloat16(v);
    h[i] = hi;
    l[i] = __float2bfloat16(v - __bfloat162float(hi));
}

// src [b][C][T] f32 -> dst [b][T][C] bf16 hi/lo
__global__ void convT_kernel(const float* __restrict__ src,
                             bf16* __restrict__ dh, bf16* __restrict__ dl) {
    __shared__ float tile[32][33];
    const int b = blockIdx.z;
    const int t0 = blockIdx.x * 32;
    const int c0 = blockIdx.y * 32;
    const float* s = src + (size_t)b * Cc * Tt;
    bf16* oh = dh + (size_t)b * Tt * Cc;
    bf16* ol = dl + (size_t)b * Tt * Cc;
    const int tx = threadIdx.x;
    const int ty = threadIdx.y;
#pragma unroll
    for (int i = ty; i < 32; i += 8)
        tile[i][tx] = s[(size_t)(c0 + i) * Tt + t0 + tx];
    __syncthreads();
#pragma unroll
    for (int i = ty; i < 32; i += 8) {
        float v = tile[tx][i];
        bf16 hi = __float2bfloat16(v);
        size_t idx = (size_t)(t0 + i) * Cc + c0 + tx;
        oh[idx] = hi;
        ol[idx] = __float2bfloat16(v - __bfloat162float(hi));
    }
}

// ---------------- bf16 split-2 tensor-core projection GEMM ----------------
// MODE 0: head layout bf16 hi/lo; MODE 1: head layout bf16 hi/lo * mask;
// MODE 2: [B,C,T] f32 * mask
#define BM 128
#define BN 128
#define BK 32
#define ROWB 80
#define TILE_B (128 * ROWB)
#define STAGE_B (4 * TILE_B)
#define PJ_SMEM (2 * STAGE_B)

template <int MODE>
__global__ void __launch_bounds__(256) proj_mma_kernel(
    const bf16* __restrict__ Ah, const bf16* __restrict__ Al,
    const float* __restrict__ bias,
    const bf16* __restrict__ Bth, const bf16* __restrict__ Btl,
    float* __restrict__ outf, bf16* __restrict__ oh, bf16* __restrict__ ol)
{
    extern __shared__ char smem[];
    const uint32_t sb = smem_to_u32(smem);
    const int tid = threadIdx.x;
    const int wid = tid >> 5;
    const int lane = tid & 31;
    const int b = blockIdx.z;
    const int row0 = blockIdx.y * BM;
    const int col0 = blockIdx.x * BN;
    const bf16* Bh = Bth + (size_t)b * Tt * Cc;
    const bf16* Bl = Btl + (size_t)b * Tt * Cc;

    const int wm = (wid >> 2) * 64;
    const int wn = (wid & 3) * 32;
    const int lr = tid >> 2;
    const int lch = tid & 3;
    const int rowA = (((lane >> 3) & 1) << 3) + (lane & 7);
    const int colA = (lane >> 4) << 3;
    const int rowB = ((lane >> 4) << 3) + (lane & 7);
    const int colB = ((lane >> 3) & 1) << 3;

    float acc[4][4][4];
#pragma unroll
    for (int mi = 0; mi < 4; mi++)
#pragma unroll
        for (int ni = 0; ni < 4; ni++)
#pragma unroll
            for (int e = 0; e < 4; e++) acc[mi][ni][e] = 0.0f;

    const int NK = Cc / BK;

    {
        uint32_t s0 = sb;
#pragma unroll
        for (int j = 0; j < 2; j++) {
            int r = lr + j * 64;
            uint32_t so = (uint32_t)(r * ROWB + lch * 16);
            int ge = lch * 8;
            CP_ASYNC16(s0 + so,              Ah + (size_t)(row0 + r) * Cc + ge);
            CP_ASYNC16(s0 + TILE_B + so,     Al + (size_t)(row0 + r) * Cc + ge);
            CP_ASYNC16(s0 + 2 * TILE_B + so, Bh + (size_t)(col0 + r) * Cc + ge);
            CP_ASYNC16(s0 + 3 * TILE_B + so, Bl + (size_t)(col0 + r) * Cc + ge);
        }
        CP_COMMIT();
    }

#pragma unroll 1
    for (int ks = 0; ks < NK; ks++) {
        const int p = ks & 1;
        if (ks + 1 < NK) {
            const int k0 = (ks + 1) * BK;
            uint32_t s0 = sb + (p ^ 1) * STAGE_B;
#pragma unroll
            for (int j = 0; j < 2; j++) {
                int r = lr + j * 64;
                uint32_t so = (uint32_t)(r * ROWB + lch * 16);
                int ge = k0 + lch * 8;
                CP_ASYNC16(s0 + so,              Ah + (size_t)(row0 + r) * Cc + ge);
                CP_ASYNC16(s0 + TILE_B + so,     Al + (size_t)(row0 + r) * Cc + ge);
                CP_ASYNC16(s0 + 2 * TILE_B + so, Bh + (size_t)(col0 + r) * Cc + ge);
                CP_ASYNC16(s0 + 3 * TILE_B + so, Bl + (size_t)(col0 + r) * Cc + ge);
            }
            CP_COMMIT();
            CP_WAIT(1);
        } else {
            CP_WAIT(0);
        }
        __syncthreads();

        const uint32_t sAh = sb + p * STAGE_B;
        const uint32_t sAl = sAh + TILE_B;
        const uint32_t sBh = sAh + 2 * TILE_B;
        const uint32_t sBl = sAh + 3 * TILE_B;

#pragma unroll
        for (int kk = 0; kk < 32; kk += 16) {
            uint32_t a_h[4][4], a_l[4][4];
#pragma unroll
            for (int mi = 0; mi < 4; mi++) {
                uint32_t off = (uint32_t)((wm + mi * 16 + rowA) * ROWB +
                                          (kk + colA) * 2);
                LDMATRIX_X4(a_h[mi][0], a_h[mi][1], a_h[mi][2], a_h[mi][3], sAh + off);
                LDMATRIX_X4(a_l[mi][0], a_l[mi][1], a_l[mi][2], a_l[mi][3], sAl + off);
            }
            uint32_t b_h[4][2], b_l[4][2];
#pragma unroll
            for (int pr = 0; pr < 2; pr++) {
                uint32_t off = (uint32_t)((wn + pr * 16 + rowB) * ROWB +
                                          (kk + colB) * 2);
                LDMATRIX_X4(b_h[2 * pr][0], b_h[2 * pr][1],
                            b_h[2 * pr + 1][0], b_h[2 * pr + 1][1], sBh + off);
                LDMATRIX_X4(b_l[2 * pr][0], b_l[2 * pr][1],
                            b_l[2 * pr + 1][0], b_l[2 * pr + 1][1], sBl + off);
            }
#pragma unroll
            for (int mi = 0; mi < 4; mi++)
#pragma unroll
                for (int ni = 0; ni < 4; ni++) {
                    MMA_BF16(acc[mi][ni], a_h[mi], b_h[ni]);
                    MMA_BF16(acc[mi][ni], a_h[mi], b_l[ni]);
                    MMA_BF16(acc[mi][ni], a_l[mi], b_h[ni]);
                }
        }
        __syncthreads();
    }

    // ---- epilogue ----
    const int g = lane >> 2;
    const int tig = lane & 3;
#pragma unroll
    for (int mi = 0; mi < 4; mi++) {
#pragma unroll
        for (int part = 0; part < 2; part++) {
            const int o = row0 + wm + mi * 16 + g + part * 8;
            const float bo = bias[o];
#pragma unroll
            for (int ni = 0; ni < 4; ni++) {
#pragma unroll
                for (int e = 0; e < 2; e++) {
                    const int t = col0 + wn + ni * 8 + tig * 2 + e;
                    float v = acc[mi][ni][part * 2 + e] + bo;
                    if (MODE == 0 || MODE == 1) {
                        if (MODE == 1) v *= g_maskf[b * Tt + t];
                        bf16 hi = __float2bfloat16(v);
                        size_t idx =
                            (((size_t)b * Hh + (o >> 6)) * Tt + t) * Dd + (o & 63);
                        oh[idx] = hi;
                        ol[idx] = __float2bfloat16(v - __bfloat162float(hi));
                    } else {
                        outf[((size_t)b * Cc + o) * Tt + t] =
                            v * g_maskf[b * Tt + t];
                    }
                }
            }
        }
    }
}

// ---------------- bf16 split-2 flash attention ----------------
// 256 threads, q-block 128 (warp = 16 q rows), 64-key tiles, D=64.
// S = qh*kh + qh*kl + ql*kh; fp32 online softmax; P split hi/lo in regs;
// O += ph*vh + ph*vl + pl*vh. Writes ctx bf16 hi/lo [b][t][c].
#define KST 72  /* smem row stride in bf16 elems (144 B) */
__global__ void __launch_bounds__(256) attn_mma_kernel(
    const bf16* __restrict__ Qh, const bf16* __restrict__ Ql,
    const bf16* __restrict__ Kh, const bf16* __restrict__ Kl,
    const bf16* __restrict__ Vh, const bf16* __restrict__ Vl,
    bf16* __restrict__ Ch, bf16* __restrict__ Cl)
{
    __shared__ bf16 sKh[64 * KST], sKl[64 * KST];
    __shared__ bf16 sVh[64 * KST], sVl[64 * KST];
    __shared__ float msk[64];

    const int tid = threadIdx.x;
    const int wid = tid >> 5;
    const int lane = tid & 31;
    const int g = lane >> 2;
    const int tig = lane & 3;
    const int bh = blockIdx.y;
    const int b = bh >> 4;
    const int q0 = blockIdx.x * 128;
    const size_t base = (size_t)bh * Tt * Dd;

    const uint32_t aKh = smem_to_u32(sKh);
    const uint32_t aKl = smem_to_u32(sKl);
    const uint32_t aVh = smem_to_u32(sVh);
    const uint32_t aVl = smem_to_u32(sVl);

    const int rowB = ((lane >> 4) << 3) + (lane & 7);
    const int colB = ((lane >> 3) & 1) << 3;
    const int vrow = (lane & 7) + ((lane >> 3) & 1) * 8;
    const int vcol = (lane >> 4) << 3;

    // ---- Q fragments (held in registers for the whole kernel) ----
    uint32_t qh[4][4], ql[4][4];
    {
        const size_t r0 = base + (size_t)(q0 + wid * 16 + g) * Dd;
        const size_t r1 = r0 + 8 * Dd;
#pragma unroll
        for (int c = 0; c < 4; c++) {
            int k0 = c * 16 + tig * 2;
            qh[c][0] = *(const uint32_t*)(Qh + r0 + k0);
            qh[c][1] = *(const uint32_t*)(Qh + r1 + k0);
            qh[c][2] = *(const uint32_t*)(Qh + r0 + k0 + 8);
            qh[c][3] = *(const uint32_t*)(Qh + r1 + k0 + 8);
            ql[c][0] = *(const uint32_t*)(Ql + r0 + k0);
            ql[c][1] = *(const uint32_t*)(Ql + r1 + k0);
            ql[c][2] = *(const uint32_t*)(Ql + r0 + k0 + 8);
            ql[c][3] = *(const uint32_t*)(Ql + r1 + k0 + 8);
        }
    }

    float oacc[8][4];
#pragma unroll
    for (int j = 0; j < 8; j++)
#pragma unroll
        for (int e = 0; e < 4; e++) oacc[j][e] = 0.0f;
    float m0 = -3.0e38f, m1 = -3.0e38f, l0 = 0.0f, l1 = 0.0f;

    const int ldrow = tid >> 2;        // 0..63
    const int ldch = tid & 3;          // 0..3 (+4)

#pragma unroll 1
    for (int kt = 0; kt < Tt; kt += 64) {
        __syncthreads();
        {
            const size_t grow = base + (size_t)(kt + ldrow) * Dd;
            const int so = ldrow * KST;
#pragma unroll
            for (int cc = 0; cc < 2; cc++) {
                int c8 = (ldch + cc * 4) * 8;
                *(uint4*)&sKh[so + c8] = *(const uint4*)(Kh + grow + c8);
                *(uint4*)&sKl[so + c8] = *(const uint4*)(Kl + grow + c8);
                *(uint4*)&sVh[so + c8] = *(const uint4*)(Vh + grow + c8);
                *(uint4*)&sVl[so + c8] = *(const uint4*)(Vl + grow + c8);
            }
            if (tid < 64) msk[tid] = g_maskf[b * Tt + kt + tid];
        }
        __syncthreads();

        // ---- S = Q K^T (split-2, 3 terms) ----
        float sacc[8][4];
#pragma unroll
        for (int j = 0; j < 8; j++)
#pragma unroll
            for (int e = 0; e < 4; e++) sacc[j][e] = 0.0f;

#pragma unroll
        for (int c = 0; c < 4; c++) {
            uint32_t kbh[8][2], kbl[8][2];
#pragma unroll
            for (int pr = 0; pr < 4; pr++) {
                uint32_t off = (uint32_t)(((pr * 16 + rowB) * KST +
                                           c * 16 + colB) * 2);
                LDMATRIX_X4(kbh[2 * pr][0], kbh[2 * pr][1],
                            kbh[2 * pr + 1][0], kbh[2 * pr + 1][1], aKh + off);
                LDMATRIX_X4(kbl[2 * pr][0], kbl[2 * pr][1],
                            kbl[2 * pr + 1][0], kbl[2 * pr + 1][1], aKl + off);
            }
#pragma unroll
            for (int j = 0; j < 8; j++) {
                MMA_BF16(sacc[j], qh[c], kbh[j]);
                MMA_BF16(sacc[j], qh[c], kbl[j]);
                MMA_BF16(sacc[j], ql[c], kbh[j]);
            }
        }

        // ---- scale + mask + online softmax ----
        float mx0 = -3.0e38f, mx1 = -3.0e38f;
#pragma unroll
        for (int j = 0; j < 8; j++) {
            float mk0 = msk[j * 8 + tig * 2];
            float mk1 = msk[j * 8 + tig * 2 + 1];
            float s0 = (mk0 != 0.0f) ? sacc[j][0] * ATT_SCALE : -1e30f;
            float s1 = (mk1 != 0.0f) ? sacc[j][1] * ATT_SCALE : -1e30f;
            float s2 = (mk0 != 0.0f) ? sacc[j][2] * ATT_SCALE : -1e30f;
            float s3 = (mk1 != 0.0f) ? sacc[j][3] * ATT_SCALE : -1e30f;
            sacc[j][0] = s0; sacc[j][1] = s1; sacc[j][2] = s2; sacc[j][3] = s3;
            mx0 = fmaxf(mx0, fmaxf(s0, s1));
            mx1 = fmaxf(mx1, fmaxf(s2, s3));
        }
        mx0 = fmaxf(mx0, __shfl_xor_sync(0xffffffffu, mx0, 1));
        mx0 = fmaxf(mx0, __shfl_xor_sync(0xffffffffu, mx0, 2));
        mx1 = fmaxf(mx1, __shfl_xor_sync(0xffffffffu, mx1, 1));
        mx1 = fmaxf(mx1, __shfl_xor_sync(0xffffffffu, mx1, 2));
        float mn0 = fmaxf(m0, mx0);
        float mn1 = fmaxf(m1, mx1);
        float sum0 = 0.0f, sum1 = 0.0f;
#pragma unroll
        for (int j = 0; j < 8; j++) {
            float p0 = __expf(sacc[j][0] - mn0);
            float p1 = __expf(sacc[j][1] - mn0);
            float p2 = __expf(sacc[j][2] - mn1);
            float p3 = __expf(sacc[j][3] - mn1);
            sacc[j][0] = p0; sacc[j][1] = p1; sacc[j][2] = p2; sacc[j][3] = p3;
            sum0 += p0 + p1;
            sum1 += p2 + p3;
        }
        sum0 += __shfl_xor_sync(0xffffffffu, sum0, 1);
        sum0 += __shfl_xor_sync(0xffffffffu, sum0, 2);
        sum1 += __shfl_xor_sync(0xffffffffu, sum1, 1);
        sum1 += __shfl_xor_sync(0xffffffffu, sum1, 2);
        float al0 = __expf(m0 - mn0);
        float al1 = __expf(m1 - mn1);
        l0 = l0 * al0 + sum0;
        l1 = l1 * al1 + sum1;
        m0 = mn0;
        m1 = mn1;
#pragma unroll
        for (int j = 0; j < 8; j++) {
            oacc[j][0] *= al0; oacc[j][1] *= al0;
            oacc[j][2] *= al1; oacc[j][3] *= al1;
        }

        // ---- O += P V (P split hi/lo in regs, 3 terms) ----
#pragma unroll
        for (int c = 0; c < 4; c++) {
            uint32_t pah[4], pal[4];
            {
                float v00 = sacc[2 * c][0],     v01 = sacc[2 * c][1];
                float v02 = sacc[2 * c][2],     v03 = sacc[2 * c][3];
                float v10 = sacc[2 * c + 1][0], v11 = sacc[2 * c + 1][1];
                float v12 = sacc[2 * c + 1][2], v13 = sacc[2 * c + 1][3];
                float h00 = __bfloat162float(__float2bfloat16(v00));
                float h01 = __bfloat162float(__float2bfloat16(v01));
                float h02 = __bfloat162float(__float2bfloat16(v02));
                float h03 = __bfloat162float(__float2bfloat16(v03));
                float h10 = __bfloat162float(__float2bfloat16(v10));
                float h11 = __bfloat162float(__float2bfloat16(v11));
                float h12 = __bfloat162float(__float2bfloat16(v12));
                float h13 = __bfloat162float(__float2bfloat16(v13));
                pah[0] = pack_bf2(h00, h01);
                pah[1] = pack_bf2(h02, h03);
                pah[2] = pack_bf2(h10, h11);
                pah[3] = pack_bf2(h12, h13);
                pal[0] = pack_bf2(v00 - h00, v01 - h01);
                pal[1] = pack_bf2(v02 - h02, v03 - h03);
                pal[2] = pack_bf2(v10 - h10, v11 - h11);
                pal[3] = pack_bf2(v12 - h12, v13 - h13);
            }
            uint32_t vbh[8][2], vbl[8][2];
#pragma unroll
            for (int ng = 0; ng < 4; ng++) {
                uint32_t off = (uint32_t)(((c * 16 + vrow) * KST +
                                           ng * 16 + vcol) * 2);
                LDMATRIX_X4T(vbh[2 * ng][0], vbh[2 * ng][1],
                             vbh[2 * ng + 1][0], vbh[2 * ng + 1][1], aVh + off);
                LDMATRIX_X4T(vbl[2 * ng][0], vbl[2 * ng][1],
                             vbl[2 * ng + 1][0], vbl[2 * ng + 1][1], aVl + off);
            }
#pragma unroll
            for (int j = 0; j < 8; j++) {
                MMA_BF16(oacc[j], pah, vbh[j]);
                MMA_BF16(oacc[j], pah, vbl[j]);
                MMA_BF16(oacc[j], pal, vbh[j]);
            }
        }
    }

    // ---- epilogue: ctx[b][t][c] bf16 hi/lo ----
    const float inv0 = 1.0f / l0;
    const float inv1 = 1.0f / l1;
    const int t0 = q0 + wid * 16 + g;
    const int cb = (bh & 15) * 64;
    const size_t o0 = ((size_t)b * Tt + t0) * Cc + cb;
    const size_t o1 = o0 + 8 * Cc;
#pragma unroll
    for (int j = 0; j < 8; j++) {
        int cc = j * 8 + tig * 2;
        float v0 = oacc[j][0] * inv0, v1 = oacc[j][1] * inv0;
        float v2 = oacc[j][2] * inv1, v3 = oacc[j][3] * inv1;
        float h0 = __bfloat162float(__float2bfloat16(v0));
        float h1 = __bfloat162float(__float2bfloat16(v1));
        float h2 = __bfloat162float(__float2bfloat16(v2));
        float h3 = __bfloat162float(__float2bfloat16(v3));
        *(uint32_t*)(Ch + o0 + cc) = pack_bf2(h0, h1);
        *(uint32_t*)(Cl + o0 + cc) = pack_bf2(v0 - h0, v1 - h1);
        *(uint32_t*)(Ch + o1 + cc) = pack_bf2(h2, h3);
        *(uint32_t*)(Cl + o1 + cc) = pack_bf2(v2 - h2, v3 - h3);
    }
}

// ---------------- mask echo (second tuple output) ----------------
__global__ void mask_out_kernel(float* __restrict__ out) {
    int i = blockIdx.x * blockDim.x + threadIdx.x;
    if (i < Bb * Tt) out[i] = g_maskf[i];
}

// ---------------- launch ----------------
extern "C" void kernel_launch(void* const* d_in, const int* in_sizes, int n_in,
                              void* d_out, int out_size)
{
    const float* x  = (const float*)d_in[0];
    const void*  mk = d_in[1];
    const float* Wq = (const float*)d_in[2];
    const float* bq = (const float*)d_in[3];
    const float* Wk = (const float*)d_in[4];
    const float* bk = (const float*)d_in[5];
    const float* Wv = (const float*)d_in[6];
    const float* bv = (const float*)d_in[7];
    const float* Wp = (const float*)d_in[8];
    const float* bp = (const float*)d_in[9];
    float* out = (float*)d_out;

    bf16 *wqh, *wql, *wkh, *wkl, *wvh, *wvl, *wph, *wpl, *xth, *xtl;
    bf16 *qhh, *qll, *khh, *kll, *vhh, *vll, *cth, *ctl;
    cudaGetSymbolAddress((void**)&wqh, g_Wqh); cudaGetSymbolAddress((void**)&wql, g_Wql);
    cudaGetSymbolAddress((void**)&wkh, g_Wkh); cudaGetSymbolAddress((void**)&wkl, g_Wkl);
    cudaGetSymbolAddress((void**)&wvh, g_Wvh); cudaGetSymbolAddress((void**)&wvl, g_Wvl);
    cudaGetSymbolAddress((void**)&wph, g_Wph); cudaGetSymbolAddress((void**)&wpl, g_Wpl);
    cudaGetSymbolAddress((void**)&xth, g_Xth); cudaGetSymbolAddress((void**)&xtl, g_Xtl);
    cudaGetSymbolAddress((void**)&qhh, g_Qh);  cudaGetSymbolAddress((void**)&qll, g_Ql);
    cudaGetSymbolAddress((void**)&khh, g_Kh);  cudaGetSymbolAddress((void**)&kll, g_Kl);
    cudaGetSymbolAddress((void**)&vhh, g_Vh);  cudaGetSymbolAddress((void**)&vll, g_Vl);
    cudaGetSymbolAddress((void**)&cth, g_Cth); cudaGetSymbolAddress((void**)&ctl, g_Ctl);

    cudaFuncSetAttribute(proj_mma_kernel<0>,
                         cudaFuncAttributeMaxDynamicSharedMemorySize, PJ_SMEM);
    cudaFuncSetAttribute(proj_mma_kernel<1>,
                         cudaFuncAttributeMaxDynamicSharedMemorySize, PJ_SMEM);
    cudaFuncSetAttribute(proj_mma_kernel<2>,
                         cudaFuncAttributeMaxDynamicSharedMemorySize, PJ_SMEM);

    mask_convert_kernel<<<1, 256>>>(mk);

    const int wblocks = Cc * Cc / 256;
    convw_kernel<<<wblocks, 256>>>(Wq, wqh, wql);
    convw_kernel<<<wblocks, 256>>>(Wk, wkh, wkl);
    convw_kernel<<<wblocks, 256>>>(Wv, wvh, wvl);
    convw_kernel<<<wblocks, 256>>>(Wp, wph, wpl);
    convT_kernel<<<dim3(Tt / 32, Cc / 32, Bb), dim3(32, 8)>>>(x, xth, xtl);

    dim3 pg(Tt / BN, Cc / BM, Bb);
    proj_mma_kernel<0><<<pg, 256, PJ_SMEM>>>(wqh, wql, bq, xth, xtl,
                                             nullptr, qhh, qll);
    proj_mma_kernel<0><<<pg, 256, PJ_SMEM>>>(wkh, wkl, bk, xth, xtl,
                                             nullptr, khh, kll);
    proj_mma_kernel<1><<<pg, 256, PJ_SMEM>>>(wvh, wvl, bv, xth, xtl,
                                             nullptr, vhh, vll);

    attn_mma_kernel<<<dim3(Tt / 128, Bb * Hh), 256>>>(qhh, qll, khh, kll,
                                                      vhh, vll, cth, ctl);

    proj_mma_kernel<2><<<pg, 256, PJ_SMEM>>>(wph, wpl, bp, cth, ctl,
                                             out, nullptr, nullptr);

    if (out_size >= Bb * Cc * Tt + Bb * Tt) {
        mask_out_kernel<<<(Bb * Tt + 255) / 256, 256>>>(out + (size_t)Bb * Cc * Tt);
    }
}

// round 5
// speedup vs baseline: 2.5864x; 1.0131x over previous
#include <cuda_runtime.h>
#include <cuda_bf16.h>
#include <cstdint>
#include <math.h>

#define Bb 2
#define Cc 1024
#define Tt 2048
#define Hh 16
#define Dd 64
#define ATT_SCALE 0.125f  /* 1/sqrt(64) */

typedef __nv_bfloat16 bf16;

// ---------------- scratch (device globals: allocation-free) ----------------
__device__ float g_maskf[Bb * Tt];
__device__ bf16 g_Wqh[Cc * Cc], g_Wql[Cc * Cc];
__device__ bf16 g_Wkh[Cc * Cc], g_Wkl[Cc * Cc];
__device__ bf16 g_Wvh[Cc * Cc], g_Wvl[Cc * Cc];
__device__ bf16 g_Wph[Cc * Cc], g_Wpl[Cc * Cc];
__device__ bf16 g_Xth[(size_t)Bb * Tt * Cc], g_Xtl[(size_t)Bb * Tt * Cc];
__device__ bf16 g_Qh[(size_t)Bb * Hh * Tt * Dd], g_Ql[(size_t)Bb * Hh * Tt * Dd];
__device__ bf16 g_Kh[(size_t)Bb * Hh * Tt * Dd], g_Kl[(size_t)Bb * Hh * Tt * Dd];
__device__ bf16 g_Vh[(size_t)Bb * Hh * Tt * Dd], g_Vl[(size_t)Bb * Hh * Tt * Dd];
__device__ bf16 g_Cth[(size_t)Bb * Tt * Cc], g_Ctl[(size_t)Bb * Tt * Cc];

// ======================= helpers =======================
__device__ __forceinline__ uint32_t smem_to_u32(const void* p) {
    uint32_t a;
    asm("{ .reg .u64 t; cvta.to.shared.u64 t, %1; cvt.u32.u64 %0, t; }"
        : "=r"(a) : "l"(p));
    return a;
}
#define CP_ASYNC16(saddr, gptr) \
    asm volatile("cp.async.cg.shared.global [%0], [%1], 16;" \
        :: "r"(saddr), "l"(gptr) : "memory")
#define CP_COMMIT() asm volatile("cp.async.commit_group;" ::: "memory")
#define CP_WAIT(N)  asm volatile("cp.async.wait_group %0;" :: "n"(N) : "memory")
#define LDMATRIX_X4(r0, r1, r2, r3, addr) \
    asm volatile("ldmatrix.sync.aligned.m8n8.x4.shared.b16 {%0,%1,%2,%3}, [%4];" \
        : "=r"(r0), "=r"(r1), "=r"(r2), "=r"(r3) : "r"(addr))
#define LDMATRIX_X4T(r0, r1, r2, r3, addr) \
    asm volatile("ldmatrix.sync.aligned.m8n8.x4.trans.shared.b16 {%0,%1,%2,%3}, [%4];" \
        : "=r"(r0), "=r"(r1), "=r"(r2), "=r"(r3) : "r"(addr))
#define MMA_BF16(c, a, b) \
    asm volatile("mma.sync.aligned.m16n8k16.row.col.f32.bf16.bf16.f32 " \
        "{%0,%1,%2,%3}, {%4,%5,%6,%7}, {%8,%9}, {%0,%1,%2,%3};" \
        : "+f"((c)[0]), "+f"((c)[1]), "+f"((c)[2]), "+f"((c)[3]) \
        : "r"((a)[0]), "r"((a)[1]), "r"((a)[2]), "r"((a)[3]), \
          "r"((b)[0]), "r"((b)[1]))

__device__ __forceinline__ uint32_t pack_bf2(float x, float y) {
    __nv_bfloat162 t = __floats2bfloat162_rn(x, y);
    return *(uint32_t*)&t;
}

// ---------------- mask normalization ----------------
__global__ void mask_convert_kernel(const void* __restrict__ mraw) {
    const int tid = threadIdx.x;
    bool isf = true, isi = true;
    const float* f = (const float*)mraw;
    const int* w = (const int*)mraw;
    for (int i = tid; i < Bb * Tt / 4; i += 256) {
        float v = f[i];
        if (!(v == 0.0f || v == 1.0f)) isf = false;
        int iv = w[i];
        if (!(iv == 0 || iv == 1)) isi = false;
    }
    int allf = __syncthreads_and(isf ? 1 : 0);
    int alli = __syncthreads_and(isi ? 1 : 0);
    int fmt = allf ? 0 : (alli ? 1 : 2);
    for (int i = tid; i < Bb * Tt; i += 256) {
        float v;
        if (fmt == 0)      v = ((const float*)mraw)[i];
        else if (fmt == 1) v = (float)((const int*)mraw)[i];
        else               v = (float)((const unsigned char*)mraw)[i];
        g_maskf[i] = (v != 0.0f) ? 1.0f : 0.0f;
    }
}

// ---------------- conversions ----------------
// All 4 weight matrices in one launch; float4-vectorized.
__global__ void convw4_kernel(
    const float* __restrict__ s0, bf16* __restrict__ h0, bf16* __restrict__ l0,
    const float* __restrict__ s1, bf16* __restrict__ h1, bf16* __restrict__ l1,
    const float* __restrict__ s2, bf16* __restrict__ h2, bf16* __restrict__ l2,
    const float* __restrict__ s3, bf16* __restrict__ h3, bf16* __restrict__ l3)
{
    const float* s;
    bf16 *h, *l;
    switch (blockIdx.y) {
        case 0:  s = s0; h = h0; l = l0; break;
        case 1:  s = s1; h = h1; l = l1; break;
        case 2:  s = s2; h = h2; l = l2; break;
        default: s = s3; h = h3; l = l3; break;
    }
    int i = (blockIdx.x * 256 + threadIdx.x) * 4;
    float4 v = *(const float4*)(s + i);
    float hx = __bfloat162float(__float2bfloat16(v.x));
    float hy = __bfloat162float(__float2bfloat16(v.y));
    float hz = __bfloat162float(__float2bfloat16(v.z));
    float hw = __bfloat162float(__float2bfloat16(v.w));
    uint2 ho, lo;
    ho.x = pack_bf2(v.x, v.y);
    ho.y = pack_bf2(v.z, v.w);
    lo.x = pack_bf2(v.x - hx, v.y - hy);
    lo.y = pack_bf2(v.z - hz, v.w - hw);
    *(uint2*)(h + i) = ho;
    *(uint2*)(l + i) = lo;
}

// src [b][C][T] f32 -> dst [b][T][C] bf16 hi/lo
__global__ void convT_kernel(const float* __restrict__ src,
                             bf16* __restrict__ dh, bf16* __restrict__ dl) {
    __shared__ float tile[32][33];
    const int b = blockIdx.z;
    const int t0 = blockIdx.x * 32;
    const int c0 = blockIdx.y * 32;
    const float* s = src + (size_t)b * Cc * Tt;
    bf16* oh = dh + (size_t)b * Tt * Cc;
    bf16* ol = dl + (size_t)b * Tt * Cc;
    const int tx = threadIdx.x;
    const int ty = threadIdx.y;
#pragma unroll
    for (int i = ty; i < 32; i += 8)
        tile[i][tx] = s[(size_t)(c0 + i) * Tt + t0 + tx];
    __syncthreads();
#pragma unroll
    for (int i = ty; i < 32; i += 8) {
        float v = tile[tx][i];
        bf16 hi = __float2bfloat16(v);
        size_t idx = (size_t)(t0 + i) * Cc + c0 + tx;
        oh[idx] = hi;
        ol[idx] = __float2bfloat16(v - __bfloat162float(hi));
    }
}

// ---------------- bf16 split-2 tensor-core projection GEMM ----------------
// 3-stage cp.async pipeline, one __syncthreads per k-step.
#define BM 128
#define BN 128
#define BK 32
#define ROWB 80
#define TILE_B (128 * ROWB)
#define STAGE_B (4 * TILE_B)      /* 40960 */
#define PJ_SMEM (3 * STAGE_B)     /* 122880 */

template <int MODE>
__global__ void __launch_bounds__(256) proj_mma_kernel(
    const bf16* __restrict__ Ah, const bf16* __restrict__ Al,
    const float* __restrict__ bias,
    const bf16* __restrict__ Bth, const bf16* __restrict__ Btl,
    float* __restrict__ outf, bf16* __restrict__ oh, bf16* __restrict__ ol)
{
    extern __shared__ char smem[];
    const uint32_t sb = smem_to_u32(smem);
    const int tid = threadIdx.x;
    const int wid = tid >> 5;
    const int lane = tid & 31;
    const int b = blockIdx.z;
    const int row0 = blockIdx.y * BM;
    const int col0 = blockIdx.x * BN;
    const bf16* Bh = Bth + (size_t)b * Tt * Cc;
    const bf16* Bl = Btl + (size_t)b * Tt * Cc;

    const int wm = (wid >> 2) * 64;
    const int wn = (wid & 3) * 32;
    const int lr = tid >> 2;
    const int lch = tid & 3;
    const int rowA = (((lane >> 3) & 1) << 3) + (lane & 7);
    const int colA = (lane >> 4) << 3;
    const int rowB = ((lane >> 4) << 3) + (lane & 7);
    const int colB = ((lane >> 3) & 1) << 3;

    float acc[4][4][4];
#pragma unroll
    for (int mi = 0; mi < 4; mi++)
#pragma unroll
        for (int ni = 0; ni < 4; ni++)
#pragma unroll
            for (int e = 0; e < 4; e++) acc[mi][ni][e] = 0.0f;

    const int NK = Cc / BK;  // 32

    auto prefetch = [&](int k0, uint32_t s0) {
#pragma unroll
        for (int j = 0; j < 2; j++) {
            int r = lr + j * 64;
            uint32_t so = (uint32_t)(r * ROWB + lch * 16);
            int ge = k0 + lch * 8;
            CP_ASYNC16(s0 + so,              Ah + (size_t)(row0 + r) * Cc + ge);
            CP_ASYNC16(s0 + TILE_B + so,     Al + (size_t)(row0 + r) * Cc + ge);
            CP_ASYNC16(s0 + 2 * TILE_B + so, Bh + (size_t)(col0 + r) * Cc + ge);
            CP_ASYNC16(s0 + 3 * TILE_B + so, Bl + (size_t)(col0 + r) * Cc + ge);
        }
    };

    prefetch(0, sb);
    CP_COMMIT();
    prefetch(BK, sb + STAGE_B);
    CP_COMMIT();

    int stage = 0;
#pragma unroll 1
    for (int ks = 0; ks < NK; ks++) {
        CP_WAIT(1);
        __syncthreads();
        if (ks + 2 < NK) {
            int ns = stage + 2;
            if (ns >= 3) ns -= 3;
            prefetch((ks + 2) * BK, sb + ns * STAGE_B);
            CP_COMMIT();
        }

        const uint32_t sAh = sb + stage * STAGE_B;
        const uint32_t sAl = sAh + TILE_B;
        const uint32_t sBh = sAh + 2 * TILE_B;
        const uint32_t sBl = sAh + 3 * TILE_B;

#pragma unroll
        for (int kk = 0; kk < 32; kk += 16) {
            uint32_t a_h[4][4], a_l[4][4];
#pragma unroll
            for (int mi = 0; mi < 4; mi++) {
                uint32_t off = (uint32_t)((wm + mi * 16 + rowA) * ROWB +
                                          (kk + colA) * 2);
                LDMATRIX_X4(a_h[mi][0], a_h[mi][1], a_h[mi][2], a_h[mi][3], sAh + off);
                LDMATRIX_X4(a_l[mi][0], a_l[mi][1], a_l[mi][2], a_l[mi][3], sAl + off);
            }
            uint32_t b_h[4][2], b_l[4][2];
#pragma unroll
            for (int pr = 0; pr < 2; pr++) {
                uint32_t off = (uint32_t)((wn + pr * 16 + rowB) * ROWB +
                                          (kk + colB) * 2);
                LDMATRIX_X4(b_h[2 * pr][0], b_h[2 * pr][1],
                            b_h[2 * pr + 1][0], b_h[2 * pr + 1][1], sBh + off);
                LDMATRIX_X4(b_l[2 * pr][0], b_l[2 * pr][1],
                            b_l[2 * pr + 1][0], b_l[2 * pr + 1][1], sBl + off);
            }
#pragma unroll
            for (int mi = 0; mi < 4; mi++)
#pragma unroll
                for (int ni = 0; ni < 4; ni++) {
                    MMA_BF16(acc[mi][ni], a_h[mi], b_h[ni]);
                    MMA_BF16(acc[mi][ni], a_h[mi], b_l[ni]);
                    MMA_BF16(acc[mi][ni], a_l[mi], b_h[ni]);
                }
        }
        stage++;
        if (stage == 3) stage = 0;
    }

    // ---- epilogue ----
    const int g = lane >> 2;
    const int tig = lane & 3;
#pragma unroll
    for (int mi = 0; mi < 4; mi++) {
#pragma unroll
        for (int part = 0; part < 2; part++) {
            const int o = row0 + wm + mi * 16 + g + part * 8;
            const float bo = bias[o];
#pragma unroll
            for (int ni = 0; ni < 4; ni++) {
#pragma unroll
                for (int e = 0; e < 2; e++) {
                    const int t = col0 + wn + ni * 8 + tig * 2 + e;
                    float v = acc[mi][ni][part * 2 + e] + bo;
                    if (MODE == 0 || MODE == 1) {
                        if (MODE == 1) v *= g_maskf[b * Tt + t];
                        bf16 hi = __float2bfloat16(v);
                        size_t idx =
                            (((size_t)b * Hh + (o >> 6)) * Tt + t) * Dd + (o & 63);
                        oh[idx] = hi;
                        ol[idx] = __float2bfloat16(v - __bfloat162float(hi));
                    } else {
                        outf[((size_t)b * Cc + o) * Tt + t] =
                            v * g_maskf[b * Tt + t];
                    }
                }
            }
        }
    }
}

// ---------------- bf16 split-2 flash attention (double-buffered) ----------------
#define KST 72                         /* smem row stride in bf16 elems (144 B) */
#define AT_TILE (64 * KST * 2)         /* 9216 B per array */
#define AT_STAGE (4 * AT_TILE + 256)   /* 37120 B: Kh,Kl,Vh,Vl + mask */
#define AT_SMEM (2 * AT_STAGE)         /* 74240 B */

__global__ void __launch_bounds__(256) attn_mma_kernel(
    const bf16* __restrict__ Qh, const bf16* __restrict__ Ql,
    const bf16* __restrict__ Kh, const bf16* __restrict__ Kl,
    const bf16* __restrict__ Vh, const bf16* __restrict__ Vl,
    bf16* __restrict__ Ch, bf16* __restrict__ Cl)
{
    extern __shared__ char dynsm[];
    const uint32_t sbase = smem_to_u32(dynsm);

    const int tid = threadIdx.x;
    const int wid = tid >> 5;
    const int lane = tid & 31;
    const int g = lane >> 2;
    const int tig = lane & 3;
    const int bh = blockIdx.y;
    const int b = bh >> 4;
    const int q0 = blockIdx.x * 128;
    const size_t base = (size_t)bh * Tt * Dd;

    const int rowB = ((lane >> 4) << 3) + (lane & 7);
    const int colB = ((lane >> 3) & 1) << 3;
    const int vrow = (lane & 7) + ((lane >> 3) & 1) * 8;
    const int vcol = (lane >> 4) << 3;

    const int ldrow = tid >> 2;        // 0..63
    const int ldch = tid & 3;          // 0..3 (+4)

    auto prefetch = [&](int kt, uint32_t st) {
        const char* gk = (const char*)(Kh + base + (size_t)(kt + ldrow) * Dd);
        const char* gkl = (const char*)(Kl + base + (size_t)(kt + ldrow) * Dd);
        const char* gv = (const char*)(Vh + base + (size_t)(kt + ldrow) * Dd);
        const char* gvl = (const char*)(Vl + base + (size_t)(kt + ldrow) * Dd);
        uint32_t so = st + (uint32_t)(ldrow * (KST * 2));
#pragma unroll
        for (int cc = 0; cc < 2; cc++) {
            uint32_t off = (uint32_t)((ldch + cc * 4) * 16);
            CP_ASYNC16(so + off,                gk + off);
            CP_ASYNC16(so + AT_TILE + off,      gkl + off);
            CP_ASYNC16(so + 2 * AT_TILE + off,  gv + off);
            CP_ASYNC16(so + 3 * AT_TILE + off,  gvl + off);
        }
        if (tid < 16) {
            const char* gm = (const char*)(g_maskf + b * Tt + kt) + tid * 16;
            CP_ASYNC16(st + 4 * AT_TILE + tid * 16, gm);
        }
    };

    // ---- Q fragments (registers, whole kernel) ----
    uint32_t qh[4][4], ql[4][4];
    {
        const size_t r0 = base + (size_t)(q0 + wid * 16 + g) * Dd;
        const size_t r1 = r0 + 8 * Dd;
#pragma unroll
        for (int c = 0; c < 4; c++) {
            int k0 = c * 16 + tig * 2;
            qh[c][0] = *(const uint32_t*)(Qh + r0 + k0);
            qh[c][1] = *(const uint32_t*)(Qh + r1 + k0);
            qh[c][2] = *(const uint32_t*)(Qh + r0 + k0 + 8);
            qh[c][3] = *(const uint32_t*)(Qh + r1 + k0 + 8);
            ql[c][0] = *(const uint32_t*)(Ql + r0 + k0);
            ql[c][1] = *(const uint32_t*)(Ql + r1 + k0);
            ql[c][2] = *(const uint32_t*)(Ql + r0 + k0 + 8);
            ql[c][3] = *(const uint32_t*)(Ql + r1 + k0 + 8);
        }
    }

    float oacc[8][4];
#pragma unroll
    for (int j = 0; j < 8; j++)
#pragma unroll
        for (int e = 0; e < 4; e++) oacc[j][e] = 0.0f;
    float m0 = -3.0e38f, m1 = -3.0e38f, l0 = 0.0f, l1 = 0.0f;

    prefetch(0, sbase);
    CP_COMMIT();

    int stage = 0;
#pragma unroll 1
    for (int kt = 0; kt < Tt; kt += 64) {
        CP_WAIT(0);
        __syncthreads();
        if (kt + 64 < Tt) {
            prefetch(kt + 64, sbase + (stage ^ 1) * AT_STAGE);
            CP_COMMIT();
        }

        const uint32_t aKh = sbase + stage * AT_STAGE;
        const uint32_t aKl = aKh + AT_TILE;
        const uint32_t aVh = aKh + 2 * AT_TILE;
        const uint32_t aVl = aKh + 3 * AT_TILE;
        const float* msk = (const float*)(dynsm + stage * AT_STAGE + 4 * AT_TILE);

        // ---- S = Q K^T (split-2, 3 terms) ----
        float sacc[8][4];
#pragma unroll
        for (int j = 0; j < 8; j++)
#pragma unroll
            for (int e = 0; e < 4; e++) sacc[j][e] = 0.0f;

#pragma unroll
        for (int c = 0; c < 4; c++) {
            uint32_t kbh[8][2], kbl[8][2];
#pragma unroll
            for (int pr = 0; pr < 4; pr++) {
                uint32_t off = (uint32_t)(((pr * 16 + rowB) * KST +
                                           c * 16 + colB) * 2);
                LDMATRIX_X4(kbh[2 * pr][0], kbh[2 * pr][1],
                            kbh[2 * pr + 1][0], kbh[2 * pr + 1][1], aKh + off);
                LDMATRIX_X4(kbl[2 * pr][0], kbl[2 * pr][1],
                            kbl[2 * pr + 1][0], kbl[2 * pr + 1][1], aKl + off);
            }
#pragma unroll
            for (int j = 0; j < 8; j++) {
                MMA_BF16(sacc[j], qh[c], kbh[j]);
                MMA_BF16(sacc[j], qh[c], kbl[j]);
                MMA_BF16(sacc[j], ql[c], kbh[j]);
            }
        }

        // ---- scale + mask + online softmax ----
        float mx0 = -3.0e38f, mx1 = -3.0e38f;
#pragma unroll
        for (int j = 0; j < 8; j++) {
            float mk0 = msk[j * 8 + tig * 2];
            float mk1 = msk[j * 8 + tig * 2 + 1];
            float s0 = (mk0 != 0.0f) ? sacc[j][0] * ATT_SCALE : -1e30f;
            float s1 = (mk1 != 0.0f) ? sacc[j][1] * ATT_SCALE : -1e30f;
            float s2 = (mk0 != 0.0f) ? sacc[j][2] * ATT_SCALE : -1e30f;
            float s3 = (mk1 != 0.0f) ? sacc[j][3] * ATT_SCALE : -1e30f;
            sacc[j][0] = s0; sacc[j][1] = s1; sacc[j][2] = s2; sacc[j][3] = s3;
            mx0 = fmaxf(mx0, fmaxf(s0, s1));
            mx1 = fmaxf(mx1, fmaxf(s2, s3));
        }
        mx0 = fmaxf(mx0, __shfl_xor_sync(0xffffffffu, mx0, 1));
        mx0 = fmaxf(mx0, __shfl_xor_sync(0xffffffffu, mx0, 2));
        mx1 = fmaxf(mx1, __shfl_xor_sync(0xffffffffu, mx1, 1));
        mx1 = fmaxf(mx1, __shfl_xor_sync(0xffffffffu, mx1, 2));
        float mn0 = fmaxf(m0, mx0);
        float mn1 = fmaxf(m1, mx1);
        float sum0 = 0.0f, sum1 = 0.0f;
#pragma unroll
        for (int j = 0; j < 8; j++) {
            float p0 = __expf(sacc[j][0] - mn0);
            float p1 = __expf(sacc[j][1] - mn0);
            float p2 = __expf(sacc[j][2] - mn1);
            float p3 = __expf(sacc[j][3] - mn1);
            sacc[j][0] = p0; sacc[j][1] = p1; sacc[j][2] = p2; sacc[j][3] = p3;
            sum0 += p0 + p1;
            sum1 += p2 + p3;
        }
        sum0 += __shfl_xor_sync(0xffffffffu, sum0, 1);
        sum0 += __shfl_xor_sync(0xffffffffu, sum0, 2);
        sum1 += __shfl_xor_sync(0xffffffffu, sum1, 1);
        sum1 += __shfl_xor_sync(0xffffffffu, sum1, 2);
        float al0 = __expf(m0 - mn0);
        float al1 = __expf(m1 - mn1);
        l0 = l0 * al0 + sum0;
        l1 = l1 * al1 + sum1;
        m0 = mn0;
        m1 = mn1;
#pragma unroll
        for (int j = 0; j < 8; j++) {
            oacc[j][0] *= al0; oacc[j][1] *= al0;
            oacc[j][2] *= al1; oacc[j][3] *= al1;
        }

        // ---- O += P V (P split hi/lo in regs, 3 terms) ----
#pragma unroll
        for (int c = 0; c < 4; c++) {
            uint32_t pah[4], pal[4];
            {
                float v00 = sacc[2 * c][0],     v01 = sacc[2 * c][1];
                float v02 = sacc[2 * c][2],     v03 = sacc[2 * c][3];
                float v10 = sacc[2 * c + 1][0], v11 = sacc[2 * c + 1][1];
                float v12 = sacc[2 * c + 1][2], v13 = sacc[2 * c + 1][3];
                float h00 = __bfloat162float(__float2bfloat16(v00));
                float h01 = __bfloat162float(__float2bfloat16(v01));
                float h02 = __bfloat162float(__float2bfloat16(v02));
                float h03 = __bfloat162float(__float2bfloat16(v03));
                float h10 = __bfloat162float(__float2bfloat16(v10));
                float h11 = __bfloat162float(__float2bfloat16(v11));
                float h12 = __bfloat162float(__float2bfloat16(v12));
                float h13 = __bfloat162float(__float2bfloat16(v13));
                pah[0] = pack_bf2(h00, h01);
                pah[1] = pack_bf2(h02, h03);
                pah[2] = pack_bf2(h10, h11);
                pah[3] = pack_bf2(h12, h13);
                pal[0] = pack_bf2(v00 - h00, v01 - h01);
                pal[1] = pack_bf2(v02 - h02, v03 - h03);
                pal[2] = pack_bf2(v10 - h10, v11 - h11);
                pal[3] = pack_bf2(v12 - h12, v13 - h13);
            }
            uint32_t vbh[8][2], vbl[8][2];
#pragma unroll
            for (int ng = 0; ng < 4; ng++) {
                uint32_t off = (uint32_t)(((c * 16 + vrow) * KST +
                                           ng * 16 + vcol) * 2);
                LDMATRIX_X4T(vbh[2 * ng][0], vbh[2 * ng][1],
                             vbh[2 * ng + 1][0], vbh[2 * ng + 1][1], aVh + off);
                LDMATRIX_X4T(vbl[2 * ng][0], vbl[2 * ng][1],
                             vbl[2 * ng + 1][0], vbl[2 * ng + 1][1], aVl + off);
            }
#pragma unroll
            for (int j = 0; j < 8; j++) {
                MMA_BF16(oacc[j], pah, vbh[j]);
                MMA_BF16(oacc[j], pah, vbl[j]);
                MMA_BF16(oacc[j], pal, vbh[j]);
            }
        }
        stage ^= 1;
    }

    // ---- epilogue: ctx[b][t][c] bf16 hi/lo ----
    const float inv0 = 1.0f / l0;
    const float inv1 = 1.0f / l1;
    const int t0 = q0 + wid * 16 + g;
    const int cb = (bh & 15) * 64;
    const size_t o0 = ((size_t)b * Tt + t0) * Cc + cb;
    const size_t o1 = o0 + 8 * Cc;
#pragma unroll
    for (int j = 0; j < 8; j++) {
        int cc = j * 8 + tig * 2;
        float v0 = oacc[j][0] * inv0, v1 = oacc[j][1] * inv0;
        float v2 = oacc[j][2] * inv1, v3 = oacc[j][3] * inv1;
        float h0 = __bfloat162float(__float2bfloat16(v0));
        float h1 = __bfloat162float(__float2bfloat16(v1));
        float h2 = __bfloat162float(__float2bfloat16(v2));
        float h3 = __bfloat162float(__float2bfloat16(v3));
        *(uint32_t*)(Ch + o0 + cc) = pack_bf2(h0, h1);
        *(uint32_t*)(Cl + o0 + cc) = pack_bf2(v0 - h0, v1 - h1);
        *(uint32_t*)(Ch + o1 + cc) = pack_bf2(h2, h3);
        *(uint32_t*)(Cl + o1 + cc) = pack_bf2(v2 - h2, v3 - h3);
    }
}

// ---------------- mask echo (second tuple output) ----------------
__global__ void mask_out_kernel(float* __restrict__ out) {
    int i = blockIdx.x * blockDim.x + threadIdx.x;
    if (i < Bb * Tt) out[i] = g_maskf[i];
}

// ---------------- launch ----------------
extern "C" void kernel_launch(void* const* d_in, const int* in_sizes, int n_in,
                              void* d_out, int out_size)
{
    const float* x  = (const float*)d_in[0];
    const void*  mk = d_in[1];
    const float* Wq = (const float*)d_in[2];
    const float* bq = (const float*)d_in[3];
    const float* Wk = (const float*)d_in[4];
    const float* bk = (const float*)d_in[5];
    const float* Wv = (const float*)d_in[6];
    const float* bv = (const float*)d_in[7];
    const float* Wp = (const float*)d_in[8];
    const float* bp = (const float*)d_in[9];
    float* out = (float*)d_out;

    bf16 *wqh, *wql, *wkh, *wkl, *wvh, *wvl, *wph, *wpl, *xth, *xtl;
    bf16 *qhh, *qll, *khh, *kll, *vhh, *vll, *cth, *ctl;
    cudaGetSymbolAddress((void**)&wqh, g_Wqh); cudaGetSymbolAddress((void**)&wql, g_Wql);
    cudaGetSymbolAddress((void**)&wkh, g_Wkh); cudaGetSymbolAddress((void**)&wkl, g_Wkl);
    cudaGetSymbolAddress((void**)&wvh, g_Wvh); cudaGetSymbolAddress((void**)&wvl, g_Wvl);
    cudaGetSymbolAddress((void**)&wph, g_Wph); cudaGetSymbolAddress((void**)&wpl, g_Wpl);
    cudaGetSymbolAddress((void**)&xth, g_Xth); cudaGetSymbolAddress((void**)&xtl, g_Xtl);
    cudaGetSymbolAddress((void**)&qhh, g_Qh);  cudaGetSymbolAddress((void**)&qll, g_Ql);
    cudaGetSymbolAddress((void**)&khh, g_Kh);  cudaGetSymbolAddress((void**)&kll, g_Kl);
    cudaGetSymbolAddress((void**)&vhh, g_Vh);  cudaGetSymbolAddress((void**)&vll, g_Vl);
    cudaGetSymbolAddress((void**)&cth, g_Cth); cudaGetSymbolAddress((void**)&ctl, g_Ctl);

    cudaFuncSetAttribute(proj_mma_kernel<0>,
                         cudaFuncAttributeMaxDynamicSharedMemorySize, PJ_SMEM);
    cudaFuncSetAttribute(proj_mma_kernel<1>,
                         cudaFuncAttributeMaxDynamicSharedMemorySize, PJ_SMEM);
    cudaFuncSetAttribute(proj_mma_kernel<2>,
                         cudaFuncAttributeMaxDynamicSharedMemorySize, PJ_SMEM);
    cudaFuncSetAttribute(attn_mma_kernel,
                         cudaFuncAttributeMaxDynamicSharedMemorySize, AT_SMEM);

    mask_convert_kernel<<<1, 256>>>(mk);

    convw4_kernel<<<dim3(Cc * Cc / 1024, 4), 256>>>(
        Wq, wqh, wql, Wk, wkh, wkl, Wv, wvh, wvl, Wp, wph, wpl);
    convT_kernel<<<dim3(Tt / 32, Cc / 32, Bb), dim3(32, 8)>>>(x, xth, xtl);

    dim3 pg(Tt / BN, Cc / BM, Bb);
    proj_mma_kernel<0><<<pg, 256, PJ_SMEM>>>(wqh, wql, bq, xth, xtl,
                                             nullptr, qhh, qll);
    proj_mma_kernel<0><<<pg, 256, PJ_SMEM>>>(wkh, wkl, bk, xth, xtl,
                                             nullptr, khh, kll);
    proj_mma_kernel<1><<<pg, 256, PJ_SMEM>>>(wvh, wvl, bv, xth, xtl,
                                             nullptr, vhh, vll);

    attn_mma_kernel<<<dim3(Tt / 128, Bb * Hh), 256, AT_SMEM>>>(
        qhh, qll, khh, kll, vhh, vll, cth, ctl);

    proj_mma_kernel<2><<<pg, 256, PJ_SMEM>>>(wph, wpl, bp, cth, ctl,
                                             out, nullptr, nullptr);

    if (out_size >= Bb * Cc * Tt + Bb * Tt) {
        mask_out_kernel<<<(Bb * Tt + 255) / 256, 256>>>(out + (size_t)Bb * Cc * Tt);
    }
}

// round 6
// speedup vs baseline: 2.7730x; 1.0722x over previous
#include <cuda_runtime.h>
#include <cuda_bf16.h>
#include <cstdint>
#include <math.h>

#define Bb 2
#define Cc 1024
#define Tt 2048
#define Hh 16
#define Dd 64
#define ATT_SCALE 0.125f  /* 1/sqrt(64) */

typedef __nv_bfloat16 bf16;

// ---------------- scratch (device globals: allocation-free) ----------------
__device__ float g_maskf[Bb * Tt];
__device__ bf16 g_Wqh[Cc * Cc], g_Wql[Cc * Cc];
__device__ bf16 g_Wkh[Cc * Cc], g_Wkl[Cc * Cc];
__device__ bf16 g_Wvh[Cc * Cc], g_Wvl[Cc * Cc];
__device__ bf16 g_Wph[Cc * Cc], g_Wpl[Cc * Cc];
__device__ bf16 g_Xth[(size_t)Bb * Tt * Cc], g_Xtl[(size_t)Bb * Tt * Cc];
__device__ bf16 g_Qh[(size_t)Bb * Hh * Tt * Dd], g_Ql[(size_t)Bb * Hh * Tt * Dd];
__device__ bf16 g_Kh[(size_t)Bb * Hh * Tt * Dd], g_Kl[(size_t)Bb * Hh * Tt * Dd];
__device__ bf16 g_Vh[(size_t)Bb * Hh * Tt * Dd], g_Vl[(size_t)Bb * Hh * Tt * Dd];
__device__ bf16 g_Cth[(size_t)Bb * Tt * Cc], g_Ctl[(size_t)Bb * Tt * Cc];

// ======================= helpers =======================
__device__ __forceinline__ uint32_t smem_to_u32(const void* p) {
    uint32_t a;
    asm("{ .reg .u64 t; cvta.to.shared.u64 t, %1; cvt.u32.u64 %0, t; }"
        : "=r"(a) : "l"(p));
    return a;
}
#define CP_ASYNC16(saddr, gptr) \
    asm volatile("cp.async.cg.shared.global [%0], [%1], 16;" \
        :: "r"(saddr), "l"(gptr) : "memory")
#define CP_COMMIT() asm volatile("cp.async.commit_group;" ::: "memory")
#define CP_WAIT(N)  asm volatile("cp.async.wait_group %0;" :: "n"(N) : "memory")
#define LDMATRIX_X4(r0, r1, r2, r3, addr) \
    asm volatile("ldmatrix.sync.aligned.m8n8.x4.shared.b16 {%0,%1,%2,%3}, [%4];" \
        : "=r"(r0), "=r"(r1), "=r"(r2), "=r"(r3) : "r"(addr))
#define LDMATRIX_X4T(r0, r1, r2, r3, addr) \
    asm volatile("ldmatrix.sync.aligned.m8n8.x4.trans.shared.b16 {%0,%1,%2,%3}, [%4];" \
        : "=r"(r0), "=r"(r1), "=r"(r2), "=r"(r3) : "r"(addr))
#define MMA_BF16(c, a, b) \
    asm volatile("mma.sync.aligned.m16n8k16.row.col.f32.bf16.bf16.f32 " \
        "{%0,%1,%2,%3}, {%4,%5,%6,%7}, {%8,%9}, {%0,%1,%2,%3};" \
        : "+f"((c)[0]), "+f"((c)[1]), "+f"((c)[2]), "+f"((c)[3]) \
        : "r"((a)[0]), "r"((a)[1]), "r"((a)[2]), "r"((a)[3]), \
          "r"((b)[0]), "r"((b)[1]))

__device__ __forceinline__ uint32_t pack_bf2(float x, float y) {
    __nv_bfloat162 t = __floats2bfloat162_rn(x, y);
    return *(uint32_t*)&t;
}

// ---------------- mask normalization ----------------
__global__ void mask_convert_kernel(const void* __restrict__ mraw) {
    const int tid = threadIdx.x;
    bool isf = true, isi = true;
    const float* f = (const float*)mraw;
    const int* w = (const int*)mraw;
    for (int i = tid; i < Bb * Tt / 4; i += 256) {
        float v = f[i];
        if (!(v == 0.0f || v == 1.0f)) isf = false;
        int iv = w[i];
        if (!(iv == 0 || iv == 1)) isi = false;
    }
    int allf = __syncthreads_and(isf ? 1 : 0);
    int alli = __syncthreads_and(isi ? 1 : 0);
    int fmt = allf ? 0 : (alli ? 1 : 2);
    for (int i = tid; i < Bb * Tt; i += 256) {
        float v;
        if (fmt == 0)      v = ((const float*)mraw)[i];
        else if (fmt == 1) v = (float)((const int*)mraw)[i];
        else               v = (float)((const unsigned char*)mraw)[i];
        g_maskf[i] = (v != 0.0f) ? 1.0f : 0.0f;
    }
}

// ---------------- conversions ----------------
__global__ void convw4_kernel(
    const float* __restrict__ s0, bf16* __restrict__ h0, bf16* __restrict__ l0,
    const float* __restrict__ s1, bf16* __restrict__ h1, bf16* __restrict__ l1,
    const float* __restrict__ s2, bf16* __restrict__ h2, bf16* __restrict__ l2,
    const float* __restrict__ s3, bf16* __restrict__ h3, bf16* __restrict__ l3)
{
    const float* s;
    bf16 *h, *l;
    switch (blockIdx.y) {
        case 0:  s = s0; h = h0; l = l0; break;
        case 1:  s = s1; h = h1; l = l1; break;
        case 2:  s = s2; h = h2; l = l2; break;
        default: s = s3; h = h3; l = l3; break;
    }
    int i = (blockIdx.x * 256 + threadIdx.x) * 4;
    float4 v = *(const float4*)(s + i);
    float hx = __bfloat162float(__float2bfloat16(v.x));
    float hy = __bfloat162float(__float2bfloat16(v.y));
    float hz = __bfloat162float(__float2bfloat16(v.z));
    float hw = __bfloat162float(__float2bfloat16(v.w));
    uint2 ho, lo;
    ho.x = pack_bf2(v.x, v.y);
    ho.y = pack_bf2(v.z, v.w);
    lo.x = pack_bf2(v.x - hx, v.y - hy);
    lo.y = pack_bf2(v.z - hz, v.w - hw);
    *(uint2*)(h + i) = ho;
    *(uint2*)(l + i) = lo;
}

// src [b][C][T] f32 -> dst [b][T][C] bf16 hi/lo
__global__ void convT_kernel(const float* __restrict__ src,
                             bf16* __restrict__ dh, bf16* __restrict__ dl) {
    __shared__ float tile[32][33];
    const int b = blockIdx.z;
    const int t0 = blockIdx.x * 32;
    const int c0 = blockIdx.y * 32;
    const float* s = src + (size_t)b * Cc * Tt;
    bf16* oh = dh + (size_t)b * Tt * Cc;
    bf16* ol = dl + (size_t)b * Tt * Cc;
    const int tx = threadIdx.x;
    const int ty = threadIdx.y;
#pragma unroll
    for (int i = ty; i < 32; i += 8)
        tile[i][tx] = s[(size_t)(c0 + i) * Tt + t0 + tx];
    __syncthreads();
#pragma unroll
    for (int i = ty; i < 32; i += 8) {
        float v = tile[tx][i];
        bf16 hi = __float2bfloat16(v);
        size_t idx = (size_t)(t0 + i) * Cc + c0 + tx;
        oh[idx] = hi;
        ol[idx] = __float2bfloat16(v - __bfloat162float(hi));
    }
}

// ---------------- bf16 split-2 tensor-core projection GEMM ----------------
// 2-stage cp.async double buffer, one __syncthreads per k-step, 2 CTA/SM.
#define BM 128
#define BN 128
#define BK 32
#define ROWB 80
#define TILE_B (128 * ROWB)
#define STAGE_B (4 * TILE_B)      /* 40960 */
#define PJ_SMEM (2 * STAGE_B)     /* 81920 */

template <int MODE>
__global__ void __launch_bounds__(256, 2) proj_mma_kernel(
    const bf16* __restrict__ Ah, const bf16* __restrict__ Al,
    const float* __restrict__ bias,
    const bf16* __restrict__ Bth, const bf16* __restrict__ Btl,
    float* __restrict__ outf, bf16* __restrict__ oh, bf16* __restrict__ ol)
{
    extern __shared__ char smem[];
    const uint32_t sb = smem_to_u32(smem);
    const int tid = threadIdx.x;
    const int wid = tid >> 5;
    const int lane = tid & 31;
    const int b = blockIdx.z;
    const int row0 = blockIdx.y * BM;
    const int col0 = blockIdx.x * BN;
    const bf16* Bh = Bth + (size_t)b * Tt * Cc;
    const bf16* Bl = Btl + (size_t)b * Tt * Cc;

    const int wm = (wid >> 2) * 64;
    const int wn = (wid & 3) * 32;
    const int lr = tid >> 2;
    const int lch = tid & 3;
    const int rowA = (((lane >> 3) & 1) << 3) + (lane & 7);
    const int colA = (lane >> 4) << 3;
    const int rowB = ((lane >> 4) << 3) + (lane & 7);
    const int colB = ((lane >> 3) & 1) << 3;

    float acc[4][4][4];
#pragma unroll
    for (int mi = 0; mi < 4; mi++)
#pragma unroll
        for (int ni = 0; ni < 4; ni++)
#pragma unroll
            for (int e = 0; e < 4; e++) acc[mi][ni][e] = 0.0f;

    const int NK = Cc / BK;  // 32

    auto prefetch = [&](int k0, uint32_t s0) {
#pragma unroll
        for (int j = 0; j < 2; j++) {
            int r = lr + j * 64;
            uint32_t so = (uint32_t)(r * ROWB + lch * 16);
            int ge = k0 + lch * 8;
            CP_ASYNC16(s0 + so,              Ah + (size_t)(row0 + r) * Cc + ge);
            CP_ASYNC16(s0 + TILE_B + so,     Al + (size_t)(row0 + r) * Cc + ge);
            CP_ASYNC16(s0 + 2 * TILE_B + so, Bh + (size_t)(col0 + r) * Cc + ge);
            CP_ASYNC16(s0 + 3 * TILE_B + so, Bl + (size_t)(col0 + r) * Cc + ge);
        }
    };

    prefetch(0, sb);
    CP_COMMIT();

    int stage = 0;
#pragma unroll 1
    for (int ks = 0; ks < NK; ks++) {
        CP_WAIT(0);
        __syncthreads();
        if (ks + 1 < NK) {
            prefetch((ks + 1) * BK, sb + (stage ^ 1) * STAGE_B);
            CP_COMMIT();
        }

        const uint32_t sAh = sb + stage * STAGE_B;
        const uint32_t sAl = sAh + TILE_B;
        const uint32_t sBh = sAh + 2 * TILE_B;
        const uint32_t sBl = sAh + 3 * TILE_B;

#pragma unroll
        for (int kk = 0; kk < 32; kk += 16) {
            uint32_t a_h[4][4], a_l[4][4];
#pragma unroll
            for (int mi = 0; mi < 4; mi++) {
                uint32_t off = (uint32_t)((wm + mi * 16 + rowA) * ROWB +
                                          (kk + colA) * 2);
                LDMATRIX_X4(a_h[mi][0], a_h[mi][1], a_h[mi][2], a_h[mi][3], sAh + off);
                LDMATRIX_X4(a_l[mi][0], a_l[mi][1], a_l[mi][2], a_l[mi][3], sAl + off);
            }
            uint32_t b_h[4][2], b_l[4][2];
#pragma unroll
            for (int pr = 0; pr < 2; pr++) {
                uint32_t off = (uint32_t)((wn + pr * 16 + rowB) * ROWB +
                                          (kk + colB) * 2);
                LDMATRIX_X4(b_h[2 * pr][0], b_h[2 * pr][1],
                            b_h[2 * pr + 1][0], b_h[2 * pr + 1][1], sBh + off);
                LDMATRIX_X4(b_l[2 * pr][0], b_l[2 * pr][1],
                            b_l[2 * pr + 1][0], b_l[2 * pr + 1][1], sBl + off);
            }
#pragma unroll
            for (int mi = 0; mi < 4; mi++)
#pragma unroll
                for (int ni = 0; ni < 4; ni++) {
                    MMA_BF16(acc[mi][ni], a_h[mi], b_h[ni]);
                    MMA_BF16(acc[mi][ni], a_h[mi], b_l[ni]);
                    MMA_BF16(acc[mi][ni], a_l[mi], b_h[ni]);
                }
        }
        stage ^= 1;
    }

    // ---- epilogue ----
    const int g = lane >> 2;
    const int tig = lane & 3;
#pragma unroll
    for (int mi = 0; mi < 4; mi++) {
#pragma unroll
        for (int part = 0; part < 2; part++) {
            const int o = row0 + wm + mi * 16 + g + part * 8;
            const float bo = bias[o];
#pragma unroll
            for (int ni = 0; ni < 4; ni++) {
#pragma unroll
                for (int e = 0; e < 2; e++) {
                    const int t = col0 + wn + ni * 8 + tig * 2 + e;
                    float v = acc[mi][ni][part * 2 + e] + bo;
                    if (MODE == 0 || MODE == 1) {
                        if (MODE == 1) v *= g_maskf[b * Tt + t];
                        bf16 hi = __float2bfloat16(v);
                        size_t idx =
                            (((size_t)b * Hh + (o >> 6)) * Tt + t) * Dd + (o & 63);
                        oh[idx] = hi;
                        ol[idx] = __float2bfloat16(v - __bfloat162float(hi));
                    } else {
                        outf[((size_t)b * Cc + o) * Tt + t] =
                            v * g_maskf[b * Tt + t];
                    }
                }
            }
        }
    }
}

// ---------------- bf16 split-2 flash attention ----------------
// 128 threads / 64 q-rows per block (warp = m16 tile), 64-key tiles,
// cp.async double-buffered K/V/mask, ~74 KB smem -> 3 blocks/SM.
#define KST 72                         /* smem row stride in bf16 elems (144 B) */
#define AT_TILE (64 * KST * 2)         /* 9216 B per array */
#define AT_STAGE (4 * AT_TILE + 256)   /* 37120 B: Kh,Kl,Vh,Vl + mask */
#define AT_SMEM (2 * AT_STAGE)         /* 74240 B */

__global__ void __launch_bounds__(128) attn_mma_kernel(
    const bf16* __restrict__ Qh, const bf16* __restrict__ Ql,
    const bf16* __restrict__ Kh, const bf16* __restrict__ Kl,
    const bf16* __restrict__ Vh, const bf16* __restrict__ Vl,
    bf16* __restrict__ Ch, bf16* __restrict__ Cl)
{
    extern __shared__ char dynsm[];
    const uint32_t sbase = smem_to_u32(dynsm);

    const int tid = threadIdx.x;
    const int wid = tid >> 5;        // 0..3
    const int lane = tid & 31;
    const int g = lane >> 2;
    const int tig = lane & 3;
    const int bh = blockIdx.y;
    const int b = bh >> 4;
    const int q0 = blockIdx.x * 64;
    const size_t base = (size_t)bh * Tt * Dd;

    const int rowB = ((lane >> 4) << 3) + (lane & 7);
    const int colB = ((lane >> 3) & 1) << 3;
    const int vrow = (lane & 7) + ((lane >> 3) & 1) * 8;
    const int vcol = (lane >> 4) << 3;

    const int ldrow = tid >> 1;      // 0..63
    const int ldhalf = tid & 1;      // 0..1: 64B each

    auto prefetch = [&](int kt, uint32_t st) {
        const char* gk  = (const char*)(Kh + base + (size_t)(kt + ldrow) * Dd);
        const char* gkl = (const char*)(Kl + base + (size_t)(kt + ldrow) * Dd);
        const char* gv  = (const char*)(Vh + base + (size_t)(kt + ldrow) * Dd);
        const char* gvl = (const char*)(Vl + base + (size_t)(kt + ldrow) * Dd);
        uint32_t so = st + (uint32_t)(ldrow * (KST * 2));
#pragma unroll
        for (int cc = 0; cc < 4; cc++) {
            uint32_t off = (uint32_t)((ldhalf * 4 + cc) * 16);
            CP_ASYNC16(so + off,                gk + off);
            CP_ASYNC16(so + AT_TILE + off,      gkl + off);
            CP_ASYNC16(so + 2 * AT_TILE + off,  gv + off);
            CP_ASYNC16(so + 3 * AT_TILE + off,  gvl + off);
        }
        if (tid < 16) {
            const char* gm = (const char*)(g_maskf + b * Tt + kt) + tid * 16;
            CP_ASYNC16(st + 4 * AT_TILE + tid * 16, gm);
        }
    };

    // ---- Q fragments (registers, whole kernel) ----
    uint32_t qh[4][4], ql[4][4];
    {
        const size_t r0 = base + (size_t)(q0 + wid * 16 + g) * Dd;
        const size_t r1 = r0 + 8 * Dd;
#pragma unroll
        for (int c = 0; c < 4; c++) {
            int k0 = c * 16 + tig * 2;
            qh[c][0] = *(const uint32_t*)(Qh + r0 + k0);
            qh[c][1] = *(const uint32_t*)(Qh + r1 + k0);
            qh[c][2] = *(const uint32_t*)(Qh + r0 + k0 + 8);
            qh[c][3] = *(const uint32_t*)(Qh + r1 + k0 + 8);
            ql[c][0] = *(const uint32_t*)(Ql + r0 + k0);
            ql[c][1] = *(const uint32_t*)(Ql + r1 + k0);
            ql[c][2] = *(const uint32_t*)(Ql + r0 + k0 + 8);
            ql[c][3] = *(const uint32_t*)(Ql + r1 + k0 + 8);
        }
    }

    float oacc[8][4];
#pragma unroll
    for (int j = 0; j < 8; j++)
#pragma unroll
        for (int e = 0; e < 4; e++) oacc[j][e] = 0.0f;
    float m0 = -3.0e38f, m1 = -3.0e38f, l0 = 0.0f, l1 = 0.0f;

    prefetch(0, sbase);
    CP_COMMIT();

    int stage = 0;
#pragma unroll 1
    for (int kt = 0; kt < Tt; kt += 64) {
        CP_WAIT(0);
        __syncthreads();
        if (kt + 64 < Tt) {
            prefetch(kt + 64, sbase + (stage ^ 1) * AT_STAGE);
            CP_COMMIT();
        }

        const uint32_t aKh = sbase + stage * AT_STAGE;
        const uint32_t aKl = aKh + AT_TILE;
        const uint32_t aVh = aKh + 2 * AT_TILE;
        const uint32_t aVl = aKh + 3 * AT_TILE;
        const float* msk = (const float*)(dynsm + stage * AT_STAGE + 4 * AT_TILE);

        // ---- S = Q K^T (split-2, 3 terms) ----
        float sacc[8][4];
#pragma unroll
        for (int j = 0; j < 8; j++)
#pragma unroll
            for (int e = 0; e < 4; e++) sacc[j][e] = 0.0f;

#pragma unroll
        for (int c = 0; c < 4; c++) {
            uint32_t kbh[8][2], kbl[8][2];
#pragma unroll
            for (int pr = 0; pr < 4; pr++) {
                uint32_t off = (uint32_t)(((pr * 16 + rowB) * KST +
                                           c * 16 + colB) * 2);
                LDMATRIX_X4(kbh[2 * pr][0], kbh[2 * pr][1],
                            kbh[2 * pr + 1][0], kbh[2 * pr + 1][1], aKh + off);
                LDMATRIX_X4(kbl[2 * pr][0], kbl[2 * pr][1],
                            kbl[2 * pr + 1][0], kbl[2 * pr + 1][1], aKl + off);
            }
#pragma unroll
            for (int j = 0; j < 8; j++) {
                MMA_BF16(sacc[j], qh[c], kbh[j]);
                MMA_BF16(sacc[j], qh[c], kbl[j]);
                MMA_BF16(sacc[j], ql[c], kbh[j]);
            }
        }

        // ---- scale + mask + online softmax ----
        float mx0 = -3.0e38f, mx1 = -3.0e38f;
#pragma unroll
        for (int j = 0; j < 8; j++) {
            float mk0 = msk[j * 8 + tig * 2];
            float mk1 = msk[j * 8 + tig * 2 + 1];
            float s0 = (mk0 != 0.0f) ? sacc[j][0] * ATT_SCALE : -1e30f;
            float s1 = (mk1 != 0.0f) ? sacc[j][1] * ATT_SCALE : -1e30f;
            float s2 = (mk0 != 0.0f) ? sacc[j][2] * ATT_SCALE : -1e30f;
            float s3 = (mk1 != 0.0f) ? sacc[j][3] * ATT_SCALE : -1e30f;
            sacc[j][0] = s0; sacc[j][1] = s1; sacc[j][2] = s2; sacc[j][3] = s3;
            mx0 = fmaxf(mx0, fmaxf(s0, s1));
            mx1 = fmaxf(mx1, fmaxf(s2, s3));
        }
        mx0 = fmaxf(mx0, __shfl_xor_sync(0xffffffffu, mx0, 1));
        mx0 = fmaxf(mx0, __shfl_xor_sync(0xffffffffu, mx0, 2));
        mx1 = fmaxf(mx1, __shfl_xor_sync(0xffffffffu, mx1, 1));
        mx1 = fmaxf(mx1, __shfl_xor_sync(0xffffffffu, mx1, 2));
        float mn0 = fmaxf(m0, mx0);
        float mn1 = fmaxf(m1, mx1);
        float sum0 = 0.0f, sum1 = 0.0f;
#pragma unroll
        for (int j = 0; j < 8; j++) {
            float p0 = __expf(sacc[j][0] - mn0);
            float p1 = __expf(sacc[j][1] - mn0);
            float p2 = __expf(sacc[j][2] - mn1);
            float p3 = __expf(sacc[j][3] - mn1);
            sacc[j][0] = p0; sacc[j][1] = p1; sacc[j][2] = p2; sacc[j][3] = p3;
            sum0 += p0 + p1;
            sum1 += p2 + p3;
        }
        sum0 += __shfl_xor_sync(0xffffffffu, sum0, 1);
        sum0 += __shfl_xor_sync(0xffffffffu, sum0, 2);
        sum1 += __shfl_xor_sync(0xffffffffu, sum1, 1);
        sum1 += __shfl_xor_sync(0xffffffffu, sum1, 2);
        float al0 = __expf(m0 - mn0);
        float al1 = __expf(m1 - mn1);
        l0 = l0 * al0 + sum0;
        l1 = l1 * al1 + sum1;
        m0 = mn0;
        m1 = mn1;
#pragma unroll
        for (int j = 0; j < 8; j++) {
            oacc[j][0] *= al0; oacc[j][1] *= al0;
            oacc[j][2] *= al1; oacc[j][3] *= al1;
        }

        // ---- O += P V (P split hi/lo in regs, 3 terms) ----
#pragma unroll
        for (int c = 0; c < 4; c++) {
            uint32_t pah[4], pal[4];
            {
                float v00 = sacc[2 * c][0],     v01 = sacc[2 * c][1];
                float v02 = sacc[2 * c][2],     v03 = sacc[2 * c][3];
                float v10 = sacc[2 * c + 1][0], v11 = sacc[2 * c + 1][1];
                float v12 = sacc[2 * c + 1][2], v13 = sacc[2 * c + 1][3];
                float h00 = __bfloat162float(__float2bfloat16(v00));
                float h01 = __bfloat162float(__float2bfloat16(v01));
                float h02 = __bfloat162float(__float2bfloat16(v02));
                float h03 = __bfloat162float(__float2bfloat16(v03));
                float h10 = __bfloat162float(__float2bfloat16(v10));
                float h11 = __bfloat162float(__float2bfloat16(v11));
                float h12 = __bfloat162float(__float2bfloat16(v12));
                float h13 = __bfloat162float(__float2bfloat16(v13));
                pah[0] = pack_bf2(h00, h01);
                pah[1] = pack_bf2(h02, h03);
                pah[2] = pack_bf2(h10, h11);
                pah[3] = pack_bf2(h12, h13);
                pal[0] = pack_bf2(v00 - h00, v01 - h01);
                pal[1] = pack_bf2(v02 - h02, v03 - h03);
                pal[2] = pack_bf2(v10 - h10, v11 - h11);
                pal[3] = pack_bf2(v12 - h12, v13 - h13);
            }
            uint32_t vbh[8][2], vbl[8][2];
#pragma unroll
            for (int ng = 0; ng < 4; ng++) {
                uint32_t off = (uint32_t)(((c * 16 + vrow) * KST +
                                           ng * 16 + vcol) * 2);
                LDMATRIX_X4T(vbh[2 * ng][0], vbh[2 * ng][1],
                             vbh[2 * ng + 1][0], vbh[2 * ng + 1][1], aVh + off);
                LDMATRIX_X4T(vbl[2 * ng][0], vbl[2 * ng][1],
                             vbl[2 * ng + 1][0], vbl[2 * ng + 1][1], aVl + off);
            }
#pragma unroll
            for (int j = 0; j < 8; j++) {
                MMA_BF16(oacc[j], pah, vbh[j]);
                MMA_BF16(oacc[j], pah, vbl[j]);
                MMA_BF16(oacc[j], pal, vbh[j]);
            }
        }
        stage ^= 1;
    }

    // ---- epilogue: ctx[b][t][c] bf16 hi/lo ----
    const float inv0 = 1.0f / l0;
    const float inv1 = 1.0f / l1;
    const int t0 = q0 + wid * 16 + g;
    const int cb = (bh & 15) * 64;
    const size_t o0 = ((size_t)b * Tt + t0) * Cc + cb;
    const size_t o1 = o0 + 8 * Cc;
#pragma unroll
    for (int j = 0; j < 8; j++) {
        int cc = j * 8 + tig * 2;
        float v0 = oacc[j][0] * inv0, v1 = oacc[j][1] * inv0;
        float v2 = oacc[j][2] * inv1, v3 = oacc[j][3] * inv1;
        float h0 = __bfloat162float(__float2bfloat16(v0));
        float h1 = __bfloat162float(__float2bfloat16(v1));
        float h2 = __bfloat162float(__float2bfloat16(v2));
        float h3 = __bfloat162float(__float2bfloat16(v3));
        *(uint32_t*)(Ch + o0 + cc) = pack_bf2(h0, h1);
        *(uint32_t*)(Cl + o0 + cc) = pack_bf2(v0 - h0, v1 - h1);
        *(uint32_t*)(Ch + o1 + cc) = pack_bf2(h2, h3);
        *(uint32_t*)(Cl + o1 + cc) = pack_bf2(v2 - h2, v3 - h3);
    }
}

// ---------------- mask echo (second tuple output) ----------------
__global__ void mask_out_kernel(float* __restrict__ out) {
    int i = blockIdx.x * blockDim.x + threadIdx.x;
    if (i < Bb * Tt) out[i] = g_maskf[i];
}

// ---------------- launch ----------------
extern "C" void kernel_launch(void* const* d_in, const int* in_sizes, int n_in,
                              void* d_out, int out_size)
{
    const float* x  = (const float*)d_in[0];
    const void*  mk = d_in[1];
    const float* Wq = (const float*)d_in[2];
    const float* bq = (const float*)d_in[3];
    const float* Wk = (const float*)d_in[4];
    const float* bk = (const float*)d_in[5];
    const float* Wv = (const float*)d_in[6];
    const float* bv = (const float*)d_in[7];
    const float* Wp = (const float*)d_in[8];
    const float* bp = (const float*)d_in[9];
    float* out = (float*)d_out;

    bf16 *wqh, *wql, *wkh, *wkl, *wvh, *wvl, *wph, *wpl, *xth, *xtl;
    bf16 *qhh, *qll, *khh, *kll, *vhh, *vll, *cth, *ctl;
    cudaGetSymbolAddress((void**)&wqh, g_Wqh); cudaGetSymbolAddress((void**)&wql, g_Wql);
    cudaGetSymbolAddress((void**)&wkh, g_Wkh); cudaGetSymbolAddress((void**)&wkl, g_Wkl);
    cudaGetSymbolAddress((void**)&wvh, g_Wvh); cudaGetSymbolAddress((void**)&wvl, g_Wvl);
    cudaGetSymbolAddress((void**)&wph, g_Wph); cudaGetSymbolAddress((void**)&wpl, g_Wpl);
    cudaGetSymbolAddress((void**)&xth, g_Xth); cudaGetSymbolAddress((void**)&xtl, g_Xtl);
    cudaGetSymbolAddress((void**)&qhh, g_Qh);  cudaGetSymbolAddress((void**)&qll, g_Ql);
    cudaGetSymbolAddress((void**)&khh, g_Kh);  cudaGetSymbolAddress((void**)&kll, g_Kl);
    cudaGetSymbolAddress((void**)&vhh, g_Vh);  cudaGetSymbolAddress((void**)&vll, g_Vl);
    cudaGetSymbolAddress((void**)&cth, g_Cth); cudaGetSymbolAddress((void**)&ctl, g_Ctl);

    cudaFuncSetAttribute(proj_mma_kernel<0>,
                         cudaFuncAttributeMaxDynamicSharedMemorySize, PJ_SMEM);
    cudaFuncSetAttribute(proj_mma_kernel<1>,
                         cudaFuncAttributeMaxDynamicSharedMemorySize, PJ_SMEM);
    cudaFuncSetAttribute(proj_mma_kernel<2>,
                         cudaFuncAttributeMaxDynamicSharedMemorySize, PJ_SMEM);
    cudaFuncSetAttribute(attn_mma_kernel,
                         cudaFuncAttributeMaxDynamicSharedMemorySize, AT_SMEM);

    mask_convert_kernel<<<1, 256>>>(mk);

    convw4_kernel<<<dim3(Cc * Cc / 1024, 4), 256>>>(
        Wq, wqh, wql, Wk, wkh, wkl, Wv, wvh, wvl, Wp, wph, wpl);
    convT_kernel<<<dim3(Tt / 32, Cc / 32, Bb), dim3(32, 8)>>>(x, xth, xtl);

    dim3 pg(Tt / BN, Cc / BM, Bb);
    proj_mma_kernel<0><<<pg, 256, PJ_SMEM>>>(wqh, wql, bq, xth, xtl,
                                             nullptr, qhh, qll);
    proj_mma_kernel<0><<<pg, 256, PJ_SMEM>>>(wkh, wkl, bk, xth, xtl,
                                             nullptr, khh, kll);
    proj_mma_kernel<1><<<pg, 256, PJ_SMEM>>>(wvh, wvl, bv, xth, xtl,
                                             nullptr, vhh, vll);

    attn_mma_kernel<<<dim3(Tt / 64, Bb * Hh), 128, AT_SMEM>>>(
        qhh, qll, khh, kll, vhh, vll, cth, ctl);

    proj_mma_kernel<2><<<pg, 256, PJ_SMEM>>>(wph, wpl, bp, cth, ctl,
                                             out, nullptr, nullptr);

    if (out_size >= Bb * Cc * Tt + Bb * Tt) {
        mask_out_kernel<<<(Bb * Tt + 255) / 256, 256>>>(out + (size_t)Bb * Cc * Tt);
    }
}

// round 7
// speedup vs baseline: 3.0090x; 1.0851x over previous
#include <cuda_runtime.h>
#include <cuda_bf16.h>
#include <cstdint>
#include <math.h>

#define Bb 2
#define Cc 1024
#define Tt 2048
#define Hh 16
#define Dd 64
#define ATT_SCALE 0.125f  /* 1/sqrt(64) */

typedef __nv_bfloat16 bf16;

// ---------------- scratch (device globals: allocation-free) ----------------
__device__ float g_maskf[Bb * Tt];
__device__ bf16 g_Wqh[Cc * Cc], g_Wql[Cc * Cc];
__device__ bf16 g_Wkh[Cc * Cc], g_Wkl[Cc * Cc];
__device__ bf16 g_Wvh[Cc * Cc], g_Wvl[Cc * Cc];
__device__ bf16 g_Wph[Cc * Cc], g_Wpl[Cc * Cc];
__device__ bf16 g_Xth[(size_t)Bb * Tt * Cc], g_Xtl[(size_t)Bb * Tt * Cc];
__device__ bf16 g_Qh[(size_t)Bb * Hh * Tt * Dd], g_Ql[(size_t)Bb * Hh * Tt * Dd];
__device__ bf16 g_Kh[(size_t)Bb * Hh * Tt * Dd], g_Kl[(size_t)Bb * Hh * Tt * Dd];
__device__ bf16 g_Vh[(size_t)Bb * Hh * Tt * Dd], g_Vl[(size_t)Bb * Hh * Tt * Dd];
__device__ bf16 g_Cth[(size_t)Bb * Tt * Cc], g_Ctl[(size_t)Bb * Tt * Cc];

// ======================= helpers =======================
__device__ __forceinline__ uint32_t smem_to_u32(const void* p) {
    uint32_t a;
    asm("{ .reg .u64 t; cvta.to.shared.u64 t, %1; cvt.u32.u64 %0, t; }"
        : "=r"(a) : "l"(p));
    return a;
}
#define CP_ASYNC16(saddr, gptr) \
    asm volatile("cp.async.cg.shared.global [%0], [%1], 16;" \
        :: "r"(saddr), "l"(gptr) : "memory")
#define CP_COMMIT() asm volatile("cp.async.commit_group;" ::: "memory")
#define CP_WAIT(N)  asm volatile("cp.async.wait_group %0;" :: "n"(N) : "memory")
#define LDMATRIX_X4(r0, r1, r2, r3, addr) \
    asm volatile("ldmatrix.sync.aligned.m8n8.x4.shared.b16 {%0,%1,%2,%3}, [%4];" \
        : "=r"(r0), "=r"(r1), "=r"(r2), "=r"(r3) : "r"(addr))
#define LDMATRIX_X4T(r0, r1, r2, r3, addr) \
    asm volatile("ldmatrix.sync.aligned.m8n8.x4.trans.shared.b16 {%0,%1,%2,%3}, [%4];" \
        : "=r"(r0), "=r"(r1), "=r"(r2), "=r"(r3) : "r"(addr))
#define MMA_BF16(c, a, b) \
    asm volatile("mma.sync.aligned.m16n8k16.row.col.f32.bf16.bf16.f32 " \
        "{%0,%1,%2,%3}, {%4,%5,%6,%7}, {%8,%9}, {%0,%1,%2,%3};" \
        : "+f"((c)[0]), "+f"((c)[1]), "+f"((c)[2]), "+f"((c)[3]) \
        : "r"((a)[0]), "r"((a)[1]), "r"((a)[2]), "r"((a)[3]), \
          "r"((b)[0]), "r"((b)[1]))

__device__ __forceinline__ uint32_t pack_bf2(float x, float y) {
    __nv_bfloat162 t = __floats2bfloat162_rn(x, y);
    return *(uint32_t*)&t;
}

// ---------------- mask normalization ----------------
__global__ void mask_convert_kernel(const void* __restrict__ mraw) {
    const int tid = threadIdx.x;
    bool isf = true, isi = true;
    const float* f = (const float*)mraw;
    const int* w = (const int*)mraw;
    for (int i = tid; i < Bb * Tt / 4; i += 256) {
        float v = f[i];
        if (!(v == 0.0f || v == 1.0f)) isf = false;
        int iv = w[i];
        if (!(iv == 0 || iv == 1)) isi = false;
    }
    int allf = __syncthreads_and(isf ? 1 : 0);
    int alli = __syncthreads_and(isi ? 1 : 0);
    int fmt = allf ? 0 : (alli ? 1 : 2);
    for (int i = tid; i < Bb * Tt; i += 256) {
        float v;
        if (fmt == 0)      v = ((const float*)mraw)[i];
        else if (fmt == 1) v = (float)((const int*)mraw)[i];
        else               v = (float)((const unsigned char*)mraw)[i];
        g_maskf[i] = (v != 0.0f) ? 1.0f : 0.0f;
    }
}

// ---------------- conversions ----------------
__global__ void convw4_kernel(
    const float* __restrict__ s0, bf16* __restrict__ h0, bf16* __restrict__ l0,
    const float* __restrict__ s1, bf16* __restrict__ h1, bf16* __restrict__ l1,
    const float* __restrict__ s2, bf16* __restrict__ h2, bf16* __restrict__ l2,
    const float* __restrict__ s3, bf16* __restrict__ h3, bf16* __restrict__ l3)
{
    const float* s;
    bf16 *h, *l;
    switch (blockIdx.y) {
        case 0:  s = s0; h = h0; l = l0; break;
        case 1:  s = s1; h = h1; l = l1; break;
        case 2:  s = s2; h = h2; l = l2; break;
        default: s = s3; h = h3; l = l3; break;
    }
    int i = (blockIdx.x * 256 + threadIdx.x) * 4;
    float4 v = *(const float4*)(s + i);
    float hx = __bfloat162float(__float2bfloat16(v.x));
    float hy = __bfloat162float(__float2bfloat16(v.y));
    float hz = __bfloat162float(__float2bfloat16(v.z));
    float hw = __bfloat162float(__float2bfloat16(v.w));
    uint2 ho, lo;
    ho.x = pack_bf2(v.x, v.y);
    ho.y = pack_bf2(v.z, v.w);
    lo.x = pack_bf2(v.x - hx, v.y - hy);
    lo.y = pack_bf2(v.z - hz, v.w - hw);
    *(uint2*)(h + i) = ho;
    *(uint2*)(l + i) = lo;
}

// src [b][C][T] f32 -> dst [b][T][C] bf16 hi/lo
__global__ void convT_kernel(const float* __restrict__ src,
                             bf16* __restrict__ dh, bf16* __restrict__ dl) {
    __shared__ float tile[32][33];
    const int b = blockIdx.z;
    const int t0 = blockIdx.x * 32;
    const int c0 = blockIdx.y * 32;
    const float* s = src + (size_t)b * Cc * Tt;
    bf16* oh = dh + (size_t)b * Tt * Cc;
    bf16* ol = dl + (size_t)b * Tt * Cc;
    const int tx = threadIdx.x;
    const int ty = threadIdx.y;
#pragma unroll
    for (int i = ty; i < 32; i += 8)
        tile[i][tx] = s[(size_t)(c0 + i) * Tt + t0 + tx];
    __syncthreads();
#pragma unroll
    for (int i = ty; i < 32; i += 8) {
        float v = tile[tx][i];
        bf16 hi = __float2bfloat16(v);
        size_t idx = (size_t)(t0 + i) * Cc + c0 + tx;
        oh[idx] = hi;
        ol[idx] = __float2bfloat16(v - __bfloat162float(hi));
    }
}

// ---------------- bf16 split-2 tensor-core projection GEMM ----------------
// 128x128 block, 4 warps of 64x64, 2-stage cp.async, term-major MMA order.
#define BM 128
#define BN 128
#define BK 32
#define ROWB 80
#define TILE_B (128 * ROWB)
#define STAGE_B (4 * TILE_B)      /* 40960 */
#define PJ_SMEM (2 * STAGE_B)     /* 81920 */

template <int MODE>
__global__ void __launch_bounds__(128, 2) proj_mma_kernel(
    const bf16* __restrict__ Ah, const bf16* __restrict__ Al,
    const float* __restrict__ bias,
    const bf16* __restrict__ Bth, const bf16* __restrict__ Btl,
    float* __restrict__ outf, bf16* __restrict__ oh, bf16* __restrict__ ol)
{
    extern __shared__ char smem[];
    const uint32_t sb = smem_to_u32(smem);
    const int tid = threadIdx.x;
    const int wid = tid >> 5;        // 0..3
    const int lane = tid & 31;
    const int b = blockIdx.z;
    const int row0 = blockIdx.y * BM;
    const int col0 = blockIdx.x * BN;
    const bf16* Bh = Bth + (size_t)b * Tt * Cc;
    const bf16* Bl = Btl + (size_t)b * Tt * Cc;

    const int wm = (wid >> 1) * 64;
    const int wn = (wid & 1) * 64;
    const int lr = tid >> 2;         // 0..31
    const int lch = tid & 3;
    const int rowA = (((lane >> 3) & 1) << 3) + (lane & 7);
    const int colA = (lane >> 4) << 3;
    const int rowB = ((lane >> 4) << 3) + (lane & 7);
    const int colB = ((lane >> 3) & 1) << 3;

    float acc[4][8][4];
#pragma unroll
    for (int mi = 0; mi < 4; mi++)
#pragma unroll
        for (int ni = 0; ni < 8; ni++)
#pragma unroll
            for (int e = 0; e < 4; e++) acc[mi][ni][e] = 0.0f;

    const int NK = Cc / BK;  // 32

    auto prefetch = [&](int k0, uint32_t s0) {
#pragma unroll
        for (int j = 0; j < 4; j++) {
            int r = lr + j * 32;
            uint32_t so = (uint32_t)(r * ROWB + lch * 16);
            int ge = k0 + lch * 8;
            CP_ASYNC16(s0 + so,              Ah + (size_t)(row0 + r) * Cc + ge);
            CP_ASYNC16(s0 + TILE_B + so,     Al + (size_t)(row0 + r) * Cc + ge);
            CP_ASYNC16(s0 + 2 * TILE_B + so, Bh + (size_t)(col0 + r) * Cc + ge);
            CP_ASYNC16(s0 + 3 * TILE_B + so, Bl + (size_t)(col0 + r) * Cc + ge);
        }
    };

    prefetch(0, sb);
    CP_COMMIT();

    int stage = 0;
#pragma unroll 1
    for (int ks = 0; ks < NK; ks++) {
        CP_WAIT(0);
        __syncthreads();
        if (ks + 1 < NK) {
            prefetch((ks + 1) * BK, sb + (stage ^ 1) * STAGE_B);
            CP_COMMIT();
        }

        const uint32_t sAh = sb + stage * STAGE_B;
        const uint32_t sAl = sAh + TILE_B;
        const uint32_t sBh = sAh + 2 * TILE_B;
        const uint32_t sBl = sAh + 3 * TILE_B;

#pragma unroll
        for (int kk = 0; kk < 32; kk += 16) {
            uint32_t a_h[4][4], a_l[4][4];
#pragma unroll
            for (int mi = 0; mi < 4; mi++) {
                uint32_t off = (uint32_t)((wm + mi * 16 + rowA) * ROWB +
                                          (kk + colA) * 2);
                LDMATRIX_X4(a_h[mi][0], a_h[mi][1], a_h[mi][2], a_h[mi][3], sAh + off);
                LDMATRIX_X4(a_l[mi][0], a_l[mi][1], a_l[mi][2], a_l[mi][3], sAl + off);
            }
            uint32_t b_h[8][2], b_l[8][2];
#pragma unroll
            for (int pr = 0; pr < 4; pr++) {
                uint32_t off = (uint32_t)((wn + pr * 16 + rowB) * ROWB +
                                          (kk + colB) * 2);
                LDMATRIX_X4(b_h[2 * pr][0], b_h[2 * pr][1],
                            b_h[2 * pr + 1][0], b_h[2 * pr + 1][1], sBh + off);
                LDMATRIX_X4(b_l[2 * pr][0], b_l[2 * pr][1],
                            b_l[2 * pr + 1][0], b_l[2 * pr + 1][1], sBl + off);
            }
            // term-major: same-acc MMAs 32 apart
#pragma unroll
            for (int mi = 0; mi < 4; mi++)
#pragma unroll
                for (int ni = 0; ni < 8; ni++)
                    MMA_BF16(acc[mi][ni], a_h[mi], b_h[ni]);
#pragma unroll
            for (int mi = 0; mi < 4; mi++)
#pragma unroll
                for (int ni = 0; ni < 8; ni++)
                    MMA_BF16(acc[mi][ni], a_h[mi], b_l[ni]);
#pragma unroll
            for (int mi = 0; mi < 4; mi++)
#pragma unroll
                for (int ni = 0; ni < 8; ni++)
                    MMA_BF16(acc[mi][ni], a_l[mi], b_h[ni]);
        }
        stage ^= 1;
    }

    // ---- epilogue ----
    const int g = lane >> 2;
    const int tig = lane & 3;
#pragma unroll
    for (int mi = 0; mi < 4; mi++) {
#pragma unroll
        for (int part = 0; part < 2; part++) {
            const int o = row0 + wm + mi * 16 + g + part * 8;
            const float bo = bias[o];
#pragma unroll
            for (int ni = 0; ni < 8; ni++) {
#pragma unroll
                for (int e = 0; e < 2; e++) {
                    const int t = col0 + wn + ni * 8 + tig * 2 + e;
                    float v = acc[mi][ni][part * 2 + e] + bo;
                    if (MODE == 0 || MODE == 1) {
                        if (MODE == 1) v *= g_maskf[b * Tt + t];
                        bf16 hi = __float2bfloat16(v);
                        size_t idx =
                            (((size_t)b * Hh + (o >> 6)) * Tt + t) * Dd + (o & 63);
                        oh[idx] = hi;
                        ol[idx] = __float2bfloat16(v - __bfloat162float(hi));
                    } else {
                        outf[((size_t)b * Cc + o) * Tt + t] =
                            v * g_maskf[b * Tt + t];
                    }
                }
            }
        }
    }
}

// ---------------- bf16 split-2 flash attention ----------------
// 128 threads / 128 q-rows per block: warp = m32 (two m16 tiles) so K AND V
// fragments amortize over 2 m-tiles. 32-key tiles, cp.async double buffer.
#define KST 72                         /* smem row stride bf16 elems (144 B) */
#define AT_TILE (32 * KST * 2)         /* 4608 B per array */
#define AT_STAGE (4 * AT_TILE + 128)   /* 18560 B: Kh,Kl,Vh,Vl + mask */
#define AT_SMEM (2 * AT_STAGE)         /* 37120 B */

__global__ void __launch_bounds__(128, 2) attn_mma_kernel(
    const bf16* __restrict__ Qh, const bf16* __restrict__ Ql,
    const bf16* __restrict__ Kh, const bf16* __restrict__ Kl,
    const bf16* __restrict__ Vh, const bf16* __restrict__ Vl,
    bf16* __restrict__ Ch, bf16* __restrict__ Cl)
{
    extern __shared__ char dynsm[];
    const uint32_t sbase = smem_to_u32(dynsm);

    const int tid = threadIdx.x;
    const int wid = tid >> 5;        // 0..3
    const int lane = tid & 31;
    const int g = lane >> 2;
    const int tig = lane & 3;
    const int bh = blockIdx.y;
    const int b = bh >> 4;
    const int q0 = blockIdx.x * 128;
    const size_t base = (size_t)bh * Tt * Dd;

    const int rowB = ((lane >> 4) << 3) + (lane & 7);
    const int colB = ((lane >> 3) & 1) << 3;
    const int vrow = (lane & 7) + ((lane >> 3) & 1) * 8;
    const int vcol = (lane >> 4) << 3;

    const int ldrow = tid >> 2;      // 0..31
    const int ldch = tid & 3;

    auto prefetch = [&](int kt, uint32_t st) {
        const char* gk  = (const char*)(Kh + base + (size_t)(kt + ldrow) * Dd);
        const char* gkl = (const char*)(Kl + base + (size_t)(kt + ldrow) * Dd);
        const char* gv  = (const char*)(Vh + base + (size_t)(kt + ldrow) * Dd);
        const char* gvl = (const char*)(Vl + base + (size_t)(kt + ldrow) * Dd);
        uint32_t so = st + (uint32_t)(ldrow * (KST * 2));
#pragma unroll
        for (int cc = 0; cc < 2; cc++) {
            uint32_t off = (uint32_t)((ldch + cc * 4) * 16);
            CP_ASYNC16(so + off,                gk + off);
            CP_ASYNC16(so + AT_TILE + off,      gkl + off);
            CP_ASYNC16(so + 2 * AT_TILE + off,  gv + off);
            CP_ASYNC16(so + 3 * AT_TILE + off,  gvl + off);
        }
        if (tid < 8) {
            const char* gm = (const char*)(g_maskf + b * Tt + kt) + tid * 16;
            CP_ASYNC16(st + 4 * AT_TILE + tid * 16, gm);
        }
    };

    // ---- Q fragments: 2 m16 tiles per warp (rows wid*32 .. +31) ----
    uint32_t qh[2][4][4], ql[2][4][4];
#pragma unroll
    for (int mi = 0; mi < 2; mi++) {
        const size_t r0 = base + (size_t)(q0 + wid * 32 + mi * 16 + g) * Dd;
        const size_t r1 = r0 + 8 * Dd;
#pragma unroll
        for (int c = 0; c < 4; c++) {
            int k0 = c * 16 + tig * 2;
            qh[mi][c][0] = *(const uint32_t*)(Qh + r0 + k0);
            qh[mi][c][1] = *(const uint32_t*)(Qh + r1 + k0);
            qh[mi][c][2] = *(const uint32_t*)(Qh + r0 + k0 + 8);
            qh[mi][c][3] = *(const uint32_t*)(Qh + r1 + k0 + 8);
            ql[mi][c][0] = *(const uint32_t*)(Ql + r0 + k0);
            ql[mi][c][1] = *(const uint32_t*)(Ql + r1 + k0);
            ql[mi][c][2] = *(const uint32_t*)(Ql + r0 + k0 + 8);
            ql[mi][c][3] = *(const uint32_t*)(Ql + r1 + k0 + 8);
        }
    }

    float oacc[2][8][4];
#pragma unroll
    for (int mi = 0; mi < 2; mi++)
#pragma unroll
        for (int j = 0; j < 8; j++)
#pragma unroll
            for (int e = 0; e < 4; e++) oacc[mi][j][e] = 0.0f;
    float mrow[2][2], lrow[2][2];
#pragma unroll
    for (int mi = 0; mi < 2; mi++) {
        mrow[mi][0] = -3.0e38f; mrow[mi][1] = -3.0e38f;
        lrow[mi][0] = 0.0f;     lrow[mi][1] = 0.0f;
    }

    prefetch(0, sbase);
    CP_COMMIT();

    int stage = 0;
#pragma unroll 1
    for (int kt = 0; kt < Tt; kt += 32) {
        CP_WAIT(0);
        __syncthreads();
        if (kt + 32 < Tt) {
            prefetch(kt + 32, sbase + (stage ^ 1) * AT_STAGE);
            CP_COMMIT();
        }

        const uint32_t aKh = sbase + stage * AT_STAGE;
        const uint32_t aKl = aKh + AT_TILE;
        const uint32_t aVh = aKh + 2 * AT_TILE;
        const uint32_t aVl = aKh + 3 * AT_TILE;
        const float* msk = (const float*)(dynsm + stage * AT_STAGE + 4 * AT_TILE);

        // ---- S = Q K^T (split-2, 3 terms, term-major) ----
        float sacc[2][4][4];
#pragma unroll
        for (int mi = 0; mi < 2; mi++)
#pragma unroll
            for (int j = 0; j < 4; j++)
#pragma unroll
                for (int e = 0; e < 4; e++) sacc[mi][j][e] = 0.0f;

#pragma unroll
        for (int c = 0; c < 4; c++) {
            uint32_t kbh[4][2], kbl[4][2];
#pragma unroll
            for (int pr = 0; pr < 2; pr++) {
                uint32_t off = (uint32_t)(((pr * 16 + rowB) * KST +
                                           c * 16 + colB) * 2);
                LDMATRIX_X4(kbh[2 * pr][0], kbh[2 * pr][1],
                            kbh[2 * pr + 1][0], kbh[2 * pr + 1][1], aKh + off);
                LDMATRIX_X4(kbl[2 * pr][0], kbl[2 * pr][1],
                            kbl[2 * pr + 1][0], kbl[2 * pr + 1][1], aKl + off);
            }
#pragma unroll
            for (int mi = 0; mi < 2; mi++)
#pragma unroll
                for (int j = 0; j < 4; j++)
                    MMA_BF16(sacc[mi][j], qh[mi][c], kbh[j]);
#pragma unroll
            for (int mi = 0; mi < 2; mi++)
#pragma unroll
                for (int j = 0; j < 4; j++)
                    MMA_BF16(sacc[mi][j], qh[mi][c], kbl[j]);
#pragma unroll
            for (int mi = 0; mi < 2; mi++)
#pragma unroll
                for (int j = 0; j < 4; j++)
                    MMA_BF16(sacc[mi][j], ql[mi][c], kbh[j]);
        }

        // ---- scale + mask + online softmax (per m-tile) ----
        float al[2][2];
#pragma unroll
        for (int mi = 0; mi < 2; mi++) {
            float mx0 = -3.0e38f, mx1 = -3.0e38f;
#pragma unroll
            for (int j = 0; j < 4; j++) {
                float mk0 = msk[j * 8 + tig * 2];
                float mk1 = msk[j * 8 + tig * 2 + 1];
                float s0 = (mk0 != 0.0f) ? sacc[mi][j][0] * ATT_SCALE : -1e30f;
                float s1 = (mk1 != 0.0f) ? sacc[mi][j][1] * ATT_SCALE : -1e30f;
                float s2 = (mk0 != 0.0f) ? sacc[mi][j][2] * ATT_SCALE : -1e30f;
                float s3 = (mk1 != 0.0f) ? sacc[mi][j][3] * ATT_SCALE : -1e30f;
                sacc[mi][j][0] = s0; sacc[mi][j][1] = s1;
                sacc[mi][j][2] = s2; sacc[mi][j][3] = s3;
                mx0 = fmaxf(mx0, fmaxf(s0, s1));
                mx1 = fmaxf(mx1, fmaxf(s2, s3));
            }
            mx0 = fmaxf(mx0, __shfl_xor_sync(0xffffffffu, mx0, 1));
            mx0 = fmaxf(mx0, __shfl_xor_sync(0xffffffffu, mx0, 2));
            mx1 = fmaxf(mx1, __shfl_xor_sync(0xffffffffu, mx1, 1));
            mx1 = fmaxf(mx1, __shfl_xor_sync(0xffffffffu, mx1, 2));
            float mn0 = fmaxf(mrow[mi][0], mx0);
            float mn1 = fmaxf(mrow[mi][1], mx1);
            float sum0 = 0.0f, sum1 = 0.0f;
#pragma unroll
            for (int j = 0; j < 4; j++) {
                float p0 = __expf(sacc[mi][j][0] - mn0);
                float p1 = __expf(sacc[mi][j][1] - mn0);
                float p2 = __expf(sacc[mi][j][2] - mn1);
                float p3 = __expf(sacc[mi][j][3] - mn1);
                sacc[mi][j][0] = p0; sacc[mi][j][1] = p1;
                sacc[mi][j][2] = p2; sacc[mi][j][3] = p3;
                sum0 += p0 + p1;
                sum1 += p2 + p3;
            }
            sum0 += __shfl_xor_sync(0xffffffffu, sum0, 1);
            sum0 += __shfl_xor_sync(0xffffffffu, sum0, 2);
            sum1 += __shfl_xor_sync(0xffffffffu, sum1, 1);
            sum1 += __shfl_xor_sync(0xffffffffu, sum1, 2);
            float a0 = __expf(mrow[mi][0] - mn0);
            float a1 = __expf(mrow[mi][1] - mn1);
            lrow[mi][0] = lrow[mi][0] * a0 + sum0;
            lrow[mi][1] = lrow[mi][1] * a1 + sum1;
            mrow[mi][0] = mn0;
            mrow[mi][1] = mn1;
            al[mi][0] = a0;
            al[mi][1] = a1;
        }
#pragma unroll
        for (int mi = 0; mi < 2; mi++)
#pragma unroll
            for (int j = 0; j < 8; j++) {
                oacc[mi][j][0] *= al[mi][0]; oacc[mi][j][1] *= al[mi][0];
                oacc[mi][j][2] *= al[mi][1]; oacc[mi][j][3] *= al[mi][1];
            }

        // ---- O += P V (V frags shared across both m-tiles) ----
#pragma unroll
        for (int kc = 0; kc < 2; kc++) {
            uint32_t vbh[8][2], vbl[8][2];
#pragma unroll
            for (int ng = 0; ng < 4; ng++) {
                uint32_t off = (uint32_t)(((kc * 16 + vrow) * KST +
                                           ng * 16 + vcol) * 2);
                LDMATRIX_X4T(vbh[2 * ng][0], vbh[2 * ng][1],
                             vbh[2 * ng + 1][0], vbh[2 * ng + 1][1], aVh + off);
                LDMATRIX_X4T(vbl[2 * ng][0], vbl[2 * ng][1],
                             vbl[2 * ng + 1][0], vbl[2 * ng + 1][1], aVl + off);
            }
            uint32_t pah[2][4], pal[2][4];
#pragma unroll
            for (int mi = 0; mi < 2; mi++) {
                float v00 = sacc[mi][2 * kc][0],     v01 = sacc[mi][2 * kc][1];
                float v02 = sacc[mi][2 * kc][2],     v03 = sacc[mi][2 * kc][3];
                float v10 = sacc[mi][2 * kc + 1][0], v11 = sacc[mi][2 * kc + 1][1];
                float v12 = sacc[mi][2 * kc + 1][2], v13 = sacc[mi][2 * kc + 1][3];
                float h00 = __bfloat162float(__float2bfloat16(v00));
                float h01 = __bfloat162float(__float2bfloat16(v01));
                float h02 = __bfloat162float(__float2bfloat16(v02));
                float h03 = __bfloat162float(__float2bfloat16(v03));
                float h10 = __bfloat162float(__float2bfloat16(v10));
                float h11 = __bfloat162float(__float2bfloat16(v11));
                float h12 = __bfloat162float(__float2bfloat16(v12));
                float h13 = __bfloat162float(__float2bfloat16(v13));
                pah[mi][0] = pack_bf2(h00, h01);
                pah[mi][1] = pack_bf2(h02, h03);
                pah[mi][2] = pack_bf2(h10, h11);
                pah[mi][3] = pack_bf2(h12, h13);
                pal[mi][0] = pack_bf2(v00 - h00, v01 - h01);
                pal[mi][1] = pack_bf2(v02 - h02, v03 - h03);
                pal[mi][2] = pack_bf2(v10 - h10, v11 - h11);
                pal[mi][3] = pack_bf2(v12 - h12, v13 - h13);
            }
#pragma unroll
            for (int mi = 0; mi < 2; mi++)
#pragma unroll
                for (int j = 0; j < 8; j++)
                    MMA_BF16(oacc[mi][j], pah[mi], vbh[j]);
#pragma unroll
            for (int mi = 0; mi < 2; mi++)
#pragma unroll
                for (int j = 0; j < 8; j++)
                    MMA_BF16(oacc[mi][j], pah[mi], vbl[j]);
#pragma unroll
            for (int mi = 0; mi < 2; mi++)
#pragma unroll
                for (int j = 0; j < 8; j++)
                    MMA_BF16(oacc[mi][j], pal[mi], vbh[j]);
        }
        stage ^= 1;
    }

    // ---- epilogue: ctx[b][t][c] bf16 hi/lo ----
    const int cb = (bh & 15) * 64;
#pragma unroll
    for (int mi = 0; mi < 2; mi++) {
        const float inv0 = 1.0f / lrow[mi][0];
        const float inv1 = 1.0f / lrow[mi][1];
        const int t0 = q0 + wid * 32 + mi * 16 + g;
        const size_t o0 = ((size_t)b * Tt + t0) * Cc + cb;
        const size_t o1 = o0 + 8 * Cc;
#pragma unroll
        for (int j = 0; j < 8; j++) {
            int cc = j * 8 + tig * 2;
            float v0 = oacc[mi][j][0] * inv0, v1 = oacc[mi][j][1] * inv0;
            float v2 = oacc[mi][j][2] * inv1, v3 = oacc[mi][j][3] * inv1;
            float h0 = __bfloat162float(__float2bfloat16(v0));
            float h1 = __bfloat162float(__float2bfloat16(v1));
            float h2 = __bfloat162float(__float2bfloat16(v2));
            float h3 = __bfloat162float(__float2bfloat16(v3));
            *(uint32_t*)(Ch + o0 + cc) = pack_bf2(h0, h1);
            *(uint32_t*)(Cl + o0 + cc) = pack_bf2(v0 - h0, v1 - h1);
            *(uint32_t*)(Ch + o1 + cc) = pack_bf2(h2, h3);
            *(uint32_t*)(Cl + o1 + cc) = pack_bf2(v2 - h2, v3 - h3);
        }
    }
}

// ---------------- mask echo (second tuple output) ----------------
__global__ void mask_out_kernel(float* __restrict__ out) {
    int i = blockIdx.x * blockDim.x + threadIdx.x;
    if (i < Bb * Tt) out[i] = g_maskf[i];
}

// ---------------- launch ----------------
extern "C" void kernel_launch(void* const* d_in, const int* in_sizes, int n_in,
                              void* d_out, int out_size)
{
    const float* x  = (const float*)d_in[0];
    const void*  mk = d_in[1];
    const float* Wq = (const float*)d_in[2];
    const float* bq = (const float*)d_in[3];
    const float* Wk = (const float*)d_in[4];
    const float* bk = (const float*)d_in[5];
    const float* Wv = (const float*)d_in[6];
    const float* bv = (const float*)d_in[7];
    const float* Wp = (const float*)d_in[8];
    const float* bp = (const float*)d_in[9];
    float* out = (float*)d_out;

    bf16 *wqh, *wql, *wkh, *wkl, *wvh, *wvl, *wph, *wpl, *xth, *xtl;
    bf16 *qhh, *qll, *khh, *kll, *vhh, *vll, *cth, *ctl;
    cudaGetSymbolAddress((void**)&wqh, g_Wqh); cudaGetSymbolAddress((void**)&wql, g_Wql);
    cudaGetSymbolAddress((void**)&wkh, g_Wkh); cudaGetSymbolAddress((void**)&wkl, g_Wkl);
    cudaGetSymbolAddress((void**)&wvh, g_Wvh); cudaGetSymbolAddress((void**)&wvl, g_Wvl);
    cudaGetSymbolAddress((void**)&wph, g_Wph); cudaGetSymbolAddress((void**)&wpl, g_Wpl);
    cudaGetSymbolAddress((void**)&xth, g_Xth); cudaGetSymbolAddress((void**)&xtl, g_Xtl);
    cudaGetSymbolAddress((void**)&qhh, g_Qh);  cudaGetSymbolAddress((void**)&qll, g_Ql);
    cudaGetSymbolAddress((void**)&khh, g_Kh);  cudaGetSymbolAddress((void**)&kll, g_Kl);
    cudaGetSymbolAddress((void**)&vhh, g_Vh);  cudaGetSymbolAddress((void**)&vll, g_Vl);
    cudaGetSymbolAddress((void**)&cth, g_Cth); cudaGetSymbolAddress((void**)&ctl, g_Ctl);

    cudaFuncSetAttribute(proj_mma_kernel<0>,
                         cudaFuncAttributeMaxDynamicSharedMemorySize, PJ_SMEM);
    cudaFuncSetAttribute(proj_mma_kernel<1>,
                         cudaFuncAttributeMaxDynamicSharedMemorySize, PJ_SMEM);
    cudaFuncSetAttribute(proj_mma_kernel<2>,
                         cudaFuncAttributeMaxDynamicSharedMemorySize, PJ_SMEM);
    cudaFuncSetAttribute(attn_mma_kernel,
                         cudaFuncAttributeMaxDynamicSharedMemorySize, AT_SMEM);

    mask_convert_kernel<<<1, 256>>>(mk);

    convw4_kernel<<<dim3(Cc * Cc / 1024, 4), 256>>>(
        Wq, wqh, wql, Wk, wkh, wkl, Wv, wvh, wvl, Wp, wph, wpl);
    convT_kernel<<<dim3(Tt / 32, Cc / 32, Bb), dim3(32, 8)>>>(x, xth, xtl);

    dim3 pg(Tt / BN, Cc / BM, Bb);
    proj_mma_kernel<0><<<pg, 128, PJ_SMEM>>>(wqh, wql, bq, xth, xtl,
                                             nullptr, qhh, qll);
    proj_mma_kernel<0><<<pg, 128, PJ_SMEM>>>(wkh, wkl, bk, xth, xtl,
                                             nullptr, khh, kll);
    proj_mma_kernel<1><<<pg, 128, PJ_SMEM>>>(wvh, wvl, bv, xth, xtl,
                                             nullptr, vhh, vll);

    attn_mma_kernel<<<dim3(Tt / 128, Bb * Hh), 128, AT_SMEM>>>(
        qhh, qll, khh, kll, vhh, vll, cth, ctl);

    proj_mma_kernel<2><<<pg, 128, PJ_SMEM>>>(wph, wpl, bp, cth, ctl,
                                             out, nullptr, nullptr);

    if (out_size >= Bb * Cc * Tt + Bb * Tt) {
        mask_out_kernel<<<(Bb * Tt + 255) / 256, 256>>>(out + (size_t)Bb * Cc * Tt);
    }
}

// round 8
// speedup vs baseline: 3.0649x; 1.0186x over previous
#include <cuda_runtime.h>
#include <cuda_bf16.h>
#include <cstdint>
#include <math.h>

#define Bb 2
#define Cc 1024
#define Tt 2048
#define Hh 16
#define Dd 64
#define ATT_SCALE 0.125f  /* 1/sqrt(64) */

typedef __nv_bfloat16 bf16;

// ---------------- scratch (device globals: allocation-free) ----------------
__device__ float g_maskf[Bb * Tt];
__device__ bf16 g_Wqh[Cc * Cc], g_Wql[Cc * Cc];
__device__ bf16 g_Wkh[Cc * Cc], g_Wkl[Cc * Cc];
__device__ bf16 g_Wvh[Cc * Cc], g_Wvl[Cc * Cc];
__device__ bf16 g_Wph[Cc * Cc], g_Wpl[Cc * Cc];
__device__ bf16 g_Xth[(size_t)Bb * Tt * Cc], g_Xtl[(size_t)Bb * Tt * Cc];
__device__ bf16 g_Qh[(size_t)Bb * Hh * Tt * Dd], g_Ql[(size_t)Bb * Hh * Tt * Dd];
__device__ bf16 g_Kh[(size_t)Bb * Hh * Tt * Dd], g_Kl[(size_t)Bb * Hh * Tt * Dd];
__device__ bf16 g_Vh[(size_t)Bb * Hh * Tt * Dd], g_Vl[(size_t)Bb * Hh * Tt * Dd];
__device__ bf16 g_Cth[(size_t)Bb * Tt * Cc], g_Ctl[(size_t)Bb * Tt * Cc];

// ======================= helpers =======================
__device__ __forceinline__ uint32_t smem_to_u32(const void* p) {
    uint32_t a;
    asm("{ .reg .u64 t; cvta.to.shared.u64 t, %1; cvt.u32.u64 %0, t; }"
        : "=r"(a) : "l"(p));
    return a;
}
#define CP_ASYNC16(saddr, gptr) \
    asm volatile("cp.async.cg.shared.global [%0], [%1], 16;" \
        :: "r"(saddr), "l"(gptr) : "memory")
#define CP_COMMIT() asm volatile("cp.async.commit_group;" ::: "memory")
#define CP_WAIT(N)  asm volatile("cp.async.wait_group %0;" :: "n"(N) : "memory")
#define LDMATRIX_X4(r0, r1, r2, r3, addr) \
    asm volatile("ldmatrix.sync.aligned.m8n8.x4.shared.b16 {%0,%1,%2,%3}, [%4];" \
        : "=r"(r0), "=r"(r1), "=r"(r2), "=r"(r3) : "r"(addr))
#define LDMATRIX_X4T(r0, r1, r2, r3, addr) \
    asm volatile("ldmatrix.sync.aligned.m8n8.x4.trans.shared.b16 {%0,%1,%2,%3}, [%4];" \
        : "=r"(r0), "=r"(r1), "=r"(r2), "=r"(r3) : "r"(addr))
#define MMA_BF16(c, a, b) \
    asm volatile("mma.sync.aligned.m16n8k16.row.col.f32.bf16.bf16.f32 " \
        "{%0,%1,%2,%3}, {%4,%5,%6,%7}, {%8,%9}, {%0,%1,%2,%3};" \
        : "+f"((c)[0]), "+f"((c)[1]), "+f"((c)[2]), "+f"((c)[3]) \
        : "r"((a)[0]), "r"((a)[1]), "r"((a)[2]), "r"((a)[3]), \
          "r"((b)[0]), "r"((b)[1]))

__device__ __forceinline__ uint32_t pack_bf2(float x, float y) {
    __nv_bfloat162 t = __floats2bfloat162_rn(x, y);
    return *(uint32_t*)&t;
}

// ---------------- mask normalization ----------------
__global__ void mask_convert_kernel(const void* __restrict__ mraw) {
    const int tid = threadIdx.x;
    bool isf = true, isi = true;
    const float* f = (const float*)mraw;
    const int* w = (const int*)mraw;
    for (int i = tid; i < Bb * Tt / 4; i += 256) {
        float v = f[i];
        if (!(v == 0.0f || v == 1.0f)) isf = false;
        int iv = w[i];
        if (!(iv == 0 || iv == 1)) isi = false;
    }
    int allf = __syncthreads_and(isf ? 1 : 0);
    int alli = __syncthreads_and(isi ? 1 : 0);
    int fmt = allf ? 0 : (alli ? 1 : 2);
    for (int i = tid; i < Bb * Tt; i += 256) {
        float v;
        if (fmt == 0)      v = ((const float*)mraw)[i];
        else if (fmt == 1) v = (float)((const int*)mraw)[i];
        else               v = (float)((const unsigned char*)mraw)[i];
        g_maskf[i] = (v != 0.0f) ? 1.0f : 0.0f;
    }
}

// ---------------- conversions ----------------
__global__ void convw4_kernel(
    const float* __restrict__ s0, const float* __restrict__ s1,
    const float* __restrict__ s2, const float* __restrict__ s3)
{
    const float* s;
    bf16 *h, *l;
    switch (blockIdx.y) {
        case 0:  s = s0; h = g_Wqh; l = g_Wql; break;
        case 1:  s = s1; h = g_Wkh; l = g_Wkl; break;
        case 2:  s = s2; h = g_Wvh; l = g_Wvl; break;
        default: s = s3; h = g_Wph; l = g_Wpl; break;
    }
    int i = (blockIdx.x * 256 + threadIdx.x) * 4;
    float4 v = *(const float4*)(s + i);
    float hx = __bfloat162float(__float2bfloat16(v.x));
    float hy = __bfloat162float(__float2bfloat16(v.y));
    float hz = __bfloat162float(__float2bfloat16(v.z));
    float hw = __bfloat162float(__float2bfloat16(v.w));
    uint2 ho, lo;
    ho.x = pack_bf2(v.x, v.y);
    ho.y = pack_bf2(v.z, v.w);
    lo.x = pack_bf2(v.x - hx, v.y - hy);
    lo.y = pack_bf2(v.z - hz, v.w - hw);
    *(uint2*)(h + i) = ho;
    *(uint2*)(l + i) = lo;
}

// src [b][C][T] f32 -> dst [b][T][C] bf16 hi/lo
__global__ void convT_kernel(const float* __restrict__ src,
                             bf16* __restrict__ dh, bf16* __restrict__ dl) {
    __shared__ float tile[32][33];
    const int b = blockIdx.z;
    const int t0 = blockIdx.x * 32;
    const int c0 = blockIdx.y * 32;
    const float* s = src + (size_t)b * Cc * Tt;
    bf16* oh = dh + (size_t)b * Tt * Cc;
    bf16* ol = dl + (size_t)b * Tt * Cc;
    const int tx = threadIdx.x;
    const int ty = threadIdx.y;
#pragma unroll
    for (int i = ty; i < 32; i += 8)
        tile[i][tx] = s[(size_t)(c0 + i) * Tt + t0 + tx];
    __syncthreads();
#pragma unroll
    for (int i = ty; i < 32; i += 8) {
        float v = tile[tx][i];
        bf16 hi = __float2bfloat16(v);
        size_t idx = (size_t)(t0 + i) * Cc + c0 + tx;
        oh[idx] = hi;
        ol[idx] = __float2bfloat16(v - __bfloat162float(hi));
    }
}

// ---------------- bf16 split-2 tensor-core projection GEMMs ----------------
// 128x128 block, 8 warps of 64x32, 2-stage cp.async, term-major MMA order,
// 2 CTA/SM (regs<=128).
#define BM 128
#define BN 128
#define BK 32
#define ROWB 80
#define TILE_B (128 * ROWB)
#define STAGE_B (4 * TILE_B)      /* 40960 */
#define PJ_SMEM (2 * STAGE_B)     /* 81920 */

// Shared GEMM body: A = weight [o][c] hi/lo, B = xT [t][c] hi/lo.
// acc produced in registers; epilogue differs per caller.
#define PROJ_BODY(AhP, AlP, BhP, BlP)                                         \
    float acc[4][4][4];                                                        \
    _Pragma("unroll")                                                          \
    for (int mi = 0; mi < 4; mi++)                                             \
        _Pragma("unroll")                                                      \
        for (int ni = 0; ni < 4; ni++)                                         \
            _Pragma("unroll")                                                  \
            for (int e = 0; e < 4; e++) acc[mi][ni][e] = 0.0f;                 \
    const int lr = tid >> 2;                                                   \
    const int lch = tid & 3;                                                   \
    const int rowA = (((lane >> 3) & 1) << 3) + (lane & 7);                    \
    const int colA = (lane >> 4) << 3;                                         \
    const int rowB2 = ((lane >> 4) << 3) + (lane & 7);                         \
    const int colB2 = ((lane >> 3) & 1) << 3;                                  \
    auto prefetch = [&](int k0, uint32_t s0) {                                 \
        _Pragma("unroll")                                                      \
        for (int j = 0; j < 2; j++) {                                          \
            int r = lr + j * 64;                                               \
            uint32_t so = (uint32_t)(r * ROWB + lch * 16);                     \
            int ge = k0 + lch * 8;                                             \
            CP_ASYNC16(s0 + so,              AhP + (size_t)(row0 + r) * Cc + ge); \
            CP_ASYNC16(s0 + TILE_B + so,     AlP + (size_t)(row0 + r) * Cc + ge); \
            CP_ASYNC16(s0 + 2 * TILE_B + so, BhP + (size_t)(col0 + r) * Cc + ge); \
            CP_ASYNC16(s0 + 3 * TILE_B + so, BlP + (size_t)(col0 + r) * Cc + ge); \
        }                                                                      \
    };                                                                         \
    prefetch(0, sb);                                                           \
    CP_COMMIT();                                                               \
    int stage = 0;                                                             \
    _Pragma("unroll 1")                                                        \
    for (int ks = 0; ks < Cc / BK; ks++) {                                     \
        CP_WAIT(0);                                                            \
        __syncthreads();                                                       \
        if (ks + 1 < Cc / BK) {                                                \
            prefetch((ks + 1) * BK, sb + (stage ^ 1) * STAGE_B);               \
            CP_COMMIT();                                                       \
        }                                                                      \
        const uint32_t sAh = sb + stage * STAGE_B;                             \
        const uint32_t sAl = sAh + TILE_B;                                     \
        const uint32_t sBh = sAh + 2 * TILE_B;                                 \
        const uint32_t sBl = sAh + 3 * TILE_B;                                 \
        _Pragma("unroll")                                                      \
        for (int kk = 0; kk < 32; kk += 16) {                                  \
            uint32_t a_h[4][4], a_l[4][4];                                     \
            _Pragma("unroll")                                                  \
            for (int mi = 0; mi < 4; mi++) {                                   \
                uint32_t off = (uint32_t)((wm + mi * 16 + rowA) * ROWB +       \
                                          (kk + colA) * 2);                    \
                LDMATRIX_X4(a_h[mi][0], a_h[mi][1], a_h[mi][2], a_h[mi][3],    \
                            sAh + off);                                        \
                LDMATRIX_X4(a_l[mi][0], a_l[mi][1], a_l[mi][2], a_l[mi][3],    \
                            sAl + off);                                        \
            }                                                                  \
            uint32_t b_h[4][2], b_l[4][2];                                     \
            _Pragma("unroll")                                                  \
            for (int pr = 0; pr < 2; pr++) {                                   \
                uint32_t off = (uint32_t)((wn + pr * 16 + rowB2) * ROWB +      \
                                          (kk + colB2) * 2);                   \
                LDMATRIX_X4(b_h[2 * pr][0], b_h[2 * pr][1],                    \
                            b_h[2 * pr + 1][0], b_h[2 * pr + 1][1], sBh + off);\
                LDMATRIX_X4(b_l[2 * pr][0], b_l[2 * pr][1],                    \
                            b_l[2 * pr + 1][0], b_l[2 * pr + 1][1], sBl + off);\
            }                                                                  \
            _Pragma("unroll")                                                  \
            for (int mi = 0; mi < 4; mi++)                                     \
                _Pragma("unroll")                                              \
                for (int ni = 0; ni < 4; ni++)                                 \
                    MMA_BF16(acc[mi][ni], a_h[mi], b_h[ni]);                   \
            _Pragma("unroll")                                                  \
            for (int mi = 0; mi < 4; mi++)                                     \
                _Pragma("unroll")                                              \
                for (int ni = 0; ni < 4; ni++)                                 \
                    MMA_BF16(acc[mi][ni], a_h[mi], b_l[ni]);                   \
            _Pragma("unroll")                                                  \
            for (int mi = 0; mi < 4; mi++)                                     \
                _Pragma("unroll")                                              \
                for (int ni = 0; ni < 4; ni++)                                 \
                    MMA_BF16(acc[mi][ni], a_l[mi], b_h[ni]);                   \
        }                                                                      \
        stage ^= 1;                                                            \
    }

// Merged Q/K/V projection. grid = (Tt/BN, Cc/BM, 6); z = mat*2 + batch.
__global__ void __launch_bounds__(256, 2) qkv_mma_kernel(
    const float* __restrict__ bq, const float* __restrict__ bk,
    const float* __restrict__ bv)
{
    extern __shared__ char smem[];
    const uint32_t sb = smem_to_u32(smem);
    const int tid = threadIdx.x;
    const int wid = tid >> 5;
    const int lane = tid & 31;
    const int z = blockIdx.z;
    const int b = z & 1;
    const int mat = z >> 1;
    const int row0 = blockIdx.y * BM;
    const int col0 = blockIdx.x * BN;

    const bf16 *Ah, *Al;
    const float* bias;
    bf16 *oh, *ol;
    bool domask;
    if (mat == 0)      { Ah = g_Wqh; Al = g_Wql; bias = bq; oh = g_Qh; ol = g_Ql; domask = false; }
    else if (mat == 1) { Ah = g_Wkh; Al = g_Wkl; bias = bk; oh = g_Kh; ol = g_Kl; domask = false; }
    else               { Ah = g_Wvh; Al = g_Wvl; bias = bv; oh = g_Vh; ol = g_Vl; domask = true; }
    const bf16* Bh = g_Xth + (size_t)b * Tt * Cc;
    const bf16* Bl = g_Xtl + (size_t)b * Tt * Cc;

    const int wm = (wid >> 2) * 64;
    const int wn = (wid & 3) * 32;

    PROJ_BODY(Ah, Al, Bh, Bl)

    // ---- epilogue: head layout bf16 hi/lo (+ optional mask) ----
    const int g = lane >> 2;
    const int tig = lane & 3;
#pragma unroll
    for (int mi = 0; mi < 4; mi++) {
#pragma unroll
        for (int part = 0; part < 2; part++) {
            const int o = row0 + wm + mi * 16 + g + part * 8;
            const float bo = bias[o];
#pragma unroll
            for (int ni = 0; ni < 4; ni++) {
#pragma unroll
                for (int e = 0; e < 2; e++) {
                    const int t = col0 + wn + ni * 8 + tig * 2 + e;
                    float v = acc[mi][ni][part * 2 + e] + bo;
                    if (domask) v *= g_maskf[b * Tt + t];
                    bf16 hi = __float2bfloat16(v);
                    size_t idx =
                        (((size_t)b * Hh + (o >> 6)) * Tt + t) * Dd + (o & 63);
                    oh[idx] = hi;
                    ol[idx] = __float2bfloat16(v - __bfloat162float(hi));
                }
            }
        }
    }
}

// Output projection: f32 out * mask. grid = (Tt/BN, Cc/BM, Bb).
__global__ void __launch_bounds__(256, 2) projp_mma_kernel(
    const float* __restrict__ bp, float* __restrict__ outf)
{
    extern __shared__ char smem[];
    const uint32_t sb = smem_to_u32(smem);
    const int tid = threadIdx.x;
    const int wid = tid >> 5;
    const int lane = tid & 31;
    const int b = blockIdx.z;
    const int row0 = blockIdx.y * BM;
    const int col0 = blockIdx.x * BN;

    const bf16* Ah = g_Wph;
    const bf16* Al = g_Wpl;
    const bf16* Bh = g_Cth + (size_t)b * Tt * Cc;
    const bf16* Bl = g_Ctl + (size_t)b * Tt * Cc;

    const int wm = (wid >> 2) * 64;
    const int wn = (wid & 3) * 32;

    PROJ_BODY(Ah, Al, Bh, Bl)

    const int g = lane >> 2;
    const int tig = lane & 3;
#pragma unroll
    for (int mi = 0; mi < 4; mi++) {
#pragma unroll
        for (int part = 0; part < 2; part++) {
            const int o = row0 + wm + mi * 16 + g + part * 8;
            const float bo = bp[o];
#pragma unroll
            for (int ni = 0; ni < 4; ni++) {
#pragma unroll
                for (int e = 0; e < 2; e++) {
                    const int t = col0 + wn + ni * 8 + tig * 2 + e;
                    float v = acc[mi][ni][part * 2 + e] + bo;
                    outf[((size_t)b * Cc + o) * Tt + t] = v * g_maskf[b * Tt + t];
                }
            }
        }
    }
}

// ---------------- bf16 split-2 flash attention (unchanged from R7) ----------
#define KST 72
#define AT_TILE (32 * KST * 2)
#define AT_STAGE (4 * AT_TILE + 128)
#define AT_SMEM (2 * AT_STAGE)

__global__ void __launch_bounds__(128, 2) attn_mma_kernel()
{
    extern __shared__ char dynsm[];
    const uint32_t sbase = smem_to_u32(dynsm);

    const int tid = threadIdx.x;
    const int wid = tid >> 5;
    const int lane = tid & 31;
    const int g = lane >> 2;
    const int tig = lane & 3;
    const int bh = blockIdx.y;
    const int b = bh >> 4;
    const int q0 = blockIdx.x * 128;
    const size_t base = (size_t)bh * Tt * Dd;

    const bf16* Qh = g_Qh; const bf16* Ql = g_Ql;
    const bf16* Kh = g_Kh; const bf16* Kl = g_Kl;
    const bf16* Vh = g_Vh; const bf16* Vl = g_Vl;
    bf16* Ch = g_Cth; bf16* Cl = g_Ctl;

    const int rowB = ((lane >> 4) << 3) + (lane & 7);
    const int colB = ((lane >> 3) & 1) << 3;
    const int vrow = (lane & 7) + ((lane >> 3) & 1) * 8;
    const int vcol = (lane >> 4) << 3;

    const int ldrow = tid >> 2;
    const int ldch = tid & 3;

    auto prefetch = [&](int kt, uint32_t st) {
        const char* gk  = (const char*)(Kh + base + (size_t)(kt + ldrow) * Dd);
        const char* gkl = (const char*)(Kl + base + (size_t)(kt + ldrow) * Dd);
        const char* gv  = (const char*)(Vh + base + (size_t)(kt + ldrow) * Dd);
        const char* gvl = (const char*)(Vl + base + (size_t)(kt + ldrow) * Dd);
        uint32_t so = st + (uint32_t)(ldrow * (KST * 2));
#pragma unroll
        for (int cc = 0; cc < 2; cc++) {
            uint32_t off = (uint32_t)((ldch + cc * 4) * 16);
            CP_ASYNC16(so + off,                gk + off);
            CP_ASYNC16(so + AT_TILE + off,      gkl + off);
            CP_ASYNC16(so + 2 * AT_TILE + off,  gv + off);
            CP_ASYNC16(so + 3 * AT_TILE + off,  gvl + off);
        }
        if (tid < 8) {
            const char* gm = (const char*)(g_maskf + b * Tt + kt) + tid * 16;
            CP_ASYNC16(st + 4 * AT_TILE + tid * 16, gm);
        }
    };

    uint32_t qh[2][4][4], ql[2][4][4];
#pragma unroll
    for (int mi = 0; mi < 2; mi++) {
        const size_t r0 = base + (size_t)(q0 + wid * 32 + mi * 16 + g) * Dd;
        const size_t r1 = r0 + 8 * Dd;
#pragma unroll
        for (int c = 0; c < 4; c++) {
            int k0 = c * 16 + tig * 2;
            qh[mi][c][0] = *(const uint32_t*)(Qh + r0 + k0);
            qh[mi][c][1] = *(const uint32_t*)(Qh + r1 + k0);
            qh[mi][c][2] = *(const uint32_t*)(Qh + r0 + k0 + 8);
            qh[mi][c][3] = *(const uint32_t*)(Qh + r1 + k0 + 8);
            ql[mi][c][0] = *(const uint32_t*)(Ql + r0 + k0);
            ql[mi][c][1] = *(const uint32_t*)(Ql + r1 + k0);
            ql[mi][c][2] = *(const uint32_t*)(Ql + r0 + k0 + 8);
            ql[mi][c][3] = *(const uint32_t*)(Ql + r1 + k0 + 8);
        }
    }

    float oacc[2][8][4];
#pragma unroll
    for (int mi = 0; mi < 2; mi++)
#pragma unroll
        for (int j = 0; j < 8; j++)
#pragma unroll
            for (int e = 0; e < 4; e++) oacc[mi][j][e] = 0.0f;
    float mrow[2][2], lrow[2][2];
#pragma unroll
    for (int mi = 0; mi < 2; mi++) {
        mrow[mi][0] = -3.0e38f; mrow[mi][1] = -3.0e38f;
        lrow[mi][0] = 0.0f;     lrow[mi][1] = 0.0f;
    }

    prefetch(0, sbase);
    CP_COMMIT();

    int stage = 0;
#pragma unroll 1
    for (int kt = 0; kt < Tt; kt += 32) {
        CP_WAIT(0);
        __syncthreads();
        if (kt + 32 < Tt) {
            prefetch(kt + 32, sbase + (stage ^ 1) * AT_STAGE);
            CP_COMMIT();
        }

        const uint32_t aKh = sbase + stage * AT_STAGE;
        const uint32_t aKl = aKh + AT_TILE;
        const uint32_t aVh = aKh + 2 * AT_TILE;
        const uint32_t aVl = aKh + 3 * AT_TILE;
        const float* msk = (const float*)(dynsm + stage * AT_STAGE + 4 * AT_TILE);

        float sacc[2][4][4];
#pragma unroll
        for (int mi = 0; mi < 2; mi++)
#pragma unroll
            for (int j = 0; j < 4; j++)
#pragma unroll
                for (int e = 0; e < 4; e++) sacc[mi][j][e] = 0.0f;

#pragma unroll
        for (int c = 0; c < 4; c++) {
            uint32_t kbh[4][2], kbl[4][2];
#pragma unroll
            for (int pr = 0; pr < 2; pr++) {
                uint32_t off = (uint32_t)(((pr * 16 + rowB) * KST +
                                           c * 16 + colB) * 2);
                LDMATRIX_X4(kbh[2 * pr][0], kbh[2 * pr][1],
                            kbh[2 * pr + 1][0], kbh[2 * pr + 1][1], aKh + off);
                LDMATRIX_X4(kbl[2 * pr][0], kbl[2 * pr][1],
                            kbl[2 * pr + 1][0], kbl[2 * pr + 1][1], aKl + off);
            }
#pragma unroll
            for (int mi = 0; mi < 2; mi++)
#pragma unroll
                for (int j = 0; j < 4; j++)
                    MMA_BF16(sacc[mi][j], qh[mi][c], kbh[j]);
#pragma unroll
            for (int mi = 0; mi < 2; mi++)
#pragma unroll
                for (int j = 0; j < 4; j++)
                    MMA_BF16(sacc[mi][j], qh[mi][c], kbl[j]);
#pragma unroll
            for (int mi = 0; mi < 2; mi++)
#pragma unroll
                for (int j = 0; j < 4; j++)
                    MMA_BF16(sacc[mi][j], ql[mi][c], kbh[j]);
        }

        float al[2][2];
#pragma unroll
        for (int mi = 0; mi < 2; mi++) {
            float mx0 = -3.0e38f, mx1 = -3.0e38f;
#pragma unroll
            for (int j = 0; j < 4; j++) {
                float mk0 = msk[j * 8 + tig * 2];
                float mk1 = msk[j * 8 + tig * 2 + 1];
                float s0 = (mk0 != 0.0f) ? sacc[mi][j][0] * ATT_SCALE : -1e30f;
                float s1 = (mk1 != 0.0f) ? sacc[mi][j][1] * ATT_SCALE : -1e30f;
                float s2 = (mk0 != 0.0f) ? sacc[mi][j][2] * ATT_SCALE : -1e30f;
                float s3 = (mk1 != 0.0f) ? sacc[mi][j][3] * ATT_SCALE : -1e30f;
                sacc[mi][j][0] = s0; sacc[mi][j][1] = s1;
                sacc[mi][j][2] = s2; sacc[mi][j][3] = s3;
                mx0 = fmaxf(mx0, fmaxf(s0, s1));
                mx1 = fmaxf(mx1, fmaxf(s2, s3));
            }
            mx0 = fmaxf(mx0, __shfl_xor_sync(0xffffffffu, mx0, 1));
            mx0 = fmaxf(mx0, __shfl_xor_sync(0xffffffffu, mx0, 2));
            mx1 = fmaxf(mx1, __shfl_xor_sync(0xffffffffu, mx1, 1));
            mx1 = fmaxf(mx1, __shfl_xor_sync(0xffffffffu, mx1, 2));
            float mn0 = fmaxf(mrow[mi][0], mx0);
            float mn1 = fmaxf(mrow[mi][1], mx1);
            float sum0 = 0.0f, sum1 = 0.0f;
#pragma unroll
            for (int j = 0; j < 4; j++) {
                float p0 = __expf(sacc[mi][j][0] - mn0);
                float p1 = __expf(sacc[mi][j][1] - mn0);
                float p2 = __expf(sacc[mi][j][2] - mn1);
                float p3 = __expf(sacc[mi][j][3] - mn1);
                sacc[mi][j][0] = p0; sacc[mi][j][1] = p1;
                sacc[mi][j][2] = p2; sacc[mi][j][3] = p3;
                sum0 += p0 + p1;
                sum1 += p2 + p3;
            }
            sum0 += __shfl_xor_sync(0xffffffffu, sum0, 1);
            sum0 += __shfl_xor_sync(0xffffffffu, sum0, 2);
            sum1 += __shfl_xor_sync(0xffffffffu, sum1, 1);
            sum1 += __shfl_xor_sync(0xffffffffu, sum1, 2);
            float a0 = __expf(mrow[mi][0] - mn0);
            float a1 = __expf(mrow[mi][1] - mn1);
            lrow[mi][0] = lrow[mi][0] * a0 + sum0;
            lrow[mi][1] = lrow[mi][1] * a1 + sum1;
            mrow[mi][0] = mn0;
            mrow[mi][1] = mn1;
            al[mi][0] = a0;
            al[mi][1] = a1;
        }
#pragma unroll
        for (int mi = 0; mi < 2; mi++)
#pragma unroll
            for (int j = 0; j < 8; j++) {
                oacc[mi][j][0] *= al[mi][0]; oacc[mi][j][1] *= al[mi][0];
                oacc[mi][j][2] *= al[mi][1]; oacc[mi][j][3] *= al[mi][1];
            }

#pragma unroll
        for (int kc = 0; kc < 2; kc++) {
            uint32_t vbh[8][2], vbl[8][2];
#pragma unroll
            for (int ng = 0; ng < 4; ng++) {
                uint32_t off = (uint32_t)(((kc * 16 + vrow) * KST +
                                           ng * 16 + vcol) * 2);
                LDMATRIX_X4T(vbh[2 * ng][0], vbh[2 * ng][1],
                             vbh[2 * ng + 1][0], vbh[2 * ng + 1][1], aVh + off);
                LDMATRIX_X4T(vbl[2 * ng][0], vbl[2 * ng][1],
                             vbl[2 * ng + 1][0], vbl[2 * ng + 1][1], aVl + off);
            }
            uint32_t pah[2][4], pal[2][4];
#pragma unroll
            for (int mi = 0; mi < 2; mi++) {
                float v00 = sacc[mi][2 * kc][0],     v01 = sacc[mi][2 * kc][1];
                float v02 = sacc[mi][2 * kc][2],     v03 = sacc[mi][2 * kc][3];
                float v10 = sacc[mi][2 * kc + 1][0], v11 = sacc[mi][2 * kc + 1][1];
                float v12 = sacc[mi][2 * kc + 1][2], v13 = sacc[mi][2 * kc + 1][3];
                float h00 = __bfloat162float(__float2bfloat16(v00));
                float h01 = __bfloat162float(__float2bfloat16(v01));
                float h02 = __bfloat162float(__float2bfloat16(v02));
                float h03 = __bfloat162float(__float2bfloat16(v03));
                float h10 = __bfloat162float(__float2bfloat16(v10));
                float h11 = __bfloat162float(__float2bfloat16(v11));
                float h12 = __bfloat162float(__float2bfloat16(v12));
                float h13 = __bfloat162float(__float2bfloat16(v13));
                pah[mi][0] = pack_bf2(h00, h01);
                pah[mi][1] = pack_bf2(h02, h03);
                pah[mi][2] = pack_bf2(h10, h11);
                pah[mi][3] = pack_bf2(h12, h13);
                pal[mi][0] = pack_bf2(v00 - h00, v01 - h01);
                pal[mi][1] = pack_bf2(v02 - h02, v03 - h03);
                pal[mi][2] = pack_bf2(v10 - h10, v11 - h11);
                pal[mi][3] = pack_bf2(v12 - h12, v13 - h13);
            }
#pragma unroll
            for (int mi = 0; mi < 2; mi++)
#pragma unroll
                for (int j = 0; j < 8; j++)
                    MMA_BF16(oacc[mi][j], pah[mi], vbh[j]);
#pragma unroll
            for (int mi = 0; mi < 2; mi++)
#pragma unroll
                for (int j = 0; j < 8; j++)
                    MMA_BF16(oacc[mi][j], pah[mi], vbl[j]);
#pragma unroll
            for (int mi = 0; mi < 2; mi++)
#pragma unroll
                for (int j = 0; j < 8; j++)
                    MMA_BF16(oacc[mi][j], pal[mi], vbh[j]);
        }
        stage ^= 1;
    }

    const int cb = (bh & 15) * 64;
#pragma unroll
    for (int mi = 0; mi < 2; mi++) {
        const float inv0 = 1.0f / lrow[mi][0];
        const float inv1 = 1.0f / lrow[mi][1];
        const int t0 = q0 + wid * 32 + mi * 16 + g;
        const size_t o0 = ((size_t)b * Tt + t0) * Cc + cb;
        const size_t o1 = o0 + 8 * Cc;
#pragma unroll
        for (int j = 0; j < 8; j++) {
            int cc = j * 8 + tig * 2;
            float v0 = oacc[mi][j][0] * inv0, v1 = oacc[mi][j][1] * inv0;
            float v2 = oacc[mi][j][2] * inv1, v3 = oacc[mi][j][3] * inv1;
            float h0 = __bfloat162float(__float2bfloat16(v0));
            float h1 = __bfloat162float(__float2bfloat16(v1));
            float h2 = __bfloat162float(__float2bfloat16(v2));
            float h3 = __bfloat162float(__float2bfloat16(v3));
            *(uint32_t*)(Ch + o0 + cc) = pack_bf2(h0, h1);
            *(uint32_t*)(Cl + o0 + cc) = pack_bf2(v0 - h0, v1 - h1);
            *(uint32_t*)(Ch + o1 + cc) = pack_bf2(h2, h3);
            *(uint32_t*)(Cl + o1 + cc) = pack_bf2(v2 - h2, v3 - h3);
        }
    }
}

// ---------------- mask echo (second tuple output) ----------------
__global__ void mask_out_kernel(float* __restrict__ out) {
    int i = blockIdx.x * blockDim.x + threadIdx.x;
    if (i < Bb * Tt) out[i] = g_maskf[i];
}

// ---------------- launch ----------------
extern "C" void kernel_launch(void* const* d_in, const int* in_sizes, int n_in,
                              void* d_out, int out_size)
{
    const float* x  = (const float*)d_in[0];
    const void*  mk = d_in[1];
    const float* Wq = (const float*)d_in[2];
    const float* bq = (const float*)d_in[3];
    const float* Wk = (const float*)d_in[4];
    const float* bk = (const float*)d_in[5];
    const float* Wv = (const float*)d_in[6];
    const float* bv = (const float*)d_in[7];
    const float* Wp = (const float*)d_in[8];
    const float* bp = (const float*)d_in[9];
    float* out = (float*)d_out;

    bf16 *xth, *xtl;
    cudaGetSymbolAddress((void**)&xth, g_Xth);
    cudaGetSymbolAddress((void**)&xtl, g_Xtl);

    cudaFuncSetAttribute(qkv_mma_kernel,
                         cudaFuncAttributeMaxDynamicSharedMemorySize, PJ_SMEM);
    cudaFuncSetAttribute(projp_mma_kernel,
                         cudaFuncAttributeMaxDynamicSharedMemorySize, PJ_SMEM);
    cudaFuncSetAttribute(attn_mma_kernel,
                         cudaFuncAttributeMaxDynamicSharedMemorySize, AT_SMEM);

    mask_convert_kernel<<<1, 256>>>(mk);

    convw4_kernel<<<dim3(Cc * Cc / 1024, 4), 256>>>(Wq, Wk, Wv, Wp);
    convT_kernel<<<dim3(Tt / 32, Cc / 32, Bb), dim3(32, 8)>>>(x, xth, xtl);

    qkv_mma_kernel<<<dim3(Tt / BN, Cc / BM, 6), 256, PJ_SMEM>>>(bq, bk, bv);

    attn_mma_kernel<<<dim3(Tt / 128, Bb * Hh), 128, AT_SMEM>>>();

    projp_mma_kernel<<<dim3(Tt / BN, Cc / BM, Bb), 256, PJ_SMEM>>>(bp, out);

    if (out_size >= Bb * Cc * Tt + Bb * Tt) {
        mask_out_kernel<<<(Bb * Tt + 255) / 256, 256>>>(out + (size_t)Bb * Cc * Tt);
    }
}